// round 6
// baseline (speedup 1.0000x reference)
#include <cuda_runtime.h>
#include <cuda_bf16.h>
#include <mma.h>
#include <cstdint>

using namespace nvcuda;

#define B_    8
#define L_    512
#define H_    12
#define D_    64
#define HID   768
#define OUTD  1536
#define MROWS 4096          // B_*L_
#define BHN   96            // B_*H_

#define NA4   (MROWS * HID / 4)     // 786432 float4 units of A
#define NW4   (HID * OUTD / 4)      // 294912 float4 units of W
#define NCV4  (NA4 + NW4)           // 1081344
#define HALF4 (NCV4 / 2)            //  540672
#define NROPE (L_ * 32)             //   16384

// Scratch (device globals — no runtime allocation allowed)
__device__ __nv_bfloat162 g_abf2[MROWS * HID / 2];
__device__ __nv_bfloat162 g_wbf2[HID * OUTD / 2];
__device__ __nv_bfloat16  g_q[BHN * L_ * D_];   // q, (bh, l, d) bf16
__device__ __nv_bfloat16  g_k[BHN * L_ * D_];   // k, (bh, l, d) bf16
__device__ float          g_sin[NROPE];
__device__ float          g_cos[NROPE];

static __device__ __forceinline__ void cp_async16(void* smem_dst, const void* gmem_src) {
    unsigned saddr = (unsigned)__cvta_generic_to_shared(smem_dst);
    asm volatile("cp.async.cg.shared.global [%0], [%1], 16;\n" :: "r"(saddr), "l"(gmem_src));
}
static __device__ __forceinline__ void cp_async_commit() {
    asm volatile("cp.async.commit_group;\n" ::: "memory");
}
static __device__ __forceinline__ void cp_async_wait1() {
    asm volatile("cp.async.wait_group 1;\n" ::: "memory");
}

// ---------------------------------------------------------------------------
// Kernel 0: convert inputs/W to bf16 + RoPE tables. 2 float4 per thread (MLP).
// ---------------------------------------------------------------------------
static __device__ __forceinline__ void conv_one(const float* __restrict__ A,
                                                const float* __restrict__ W, int j) {
    if (j < NA4) {
        float4 v = reinterpret_cast<const float4*>(A)[j];
        __nv_bfloat162 lo = __floats2bfloat162_rn(v.x, v.y);
        __nv_bfloat162 hi = __floats2bfloat162_rn(v.z, v.w);
        reinterpret_cast<uint2*>(g_abf2)[j] =
            make_uint2(*reinterpret_cast<unsigned*>(&lo), *reinterpret_cast<unsigned*>(&hi));
    } else {
        int t = j - NA4;
        float4 v = reinterpret_cast<const float4*>(W)[t];
        __nv_bfloat162 lo = __floats2bfloat162_rn(v.x, v.y);
        __nv_bfloat162 hi = __floats2bfloat162_rn(v.z, v.w);
        reinterpret_cast<uint2*>(g_wbf2)[t] =
            make_uint2(*reinterpret_cast<unsigned*>(&lo), *reinterpret_cast<unsigned*>(&hi));
    }
}

__global__ __launch_bounds__(256) void prep_kernel(const float* __restrict__ A,
                                                   const float* __restrict__ W) {
    int idx = blockIdx.x * 256 + threadIdx.x;
    if (idx < HALF4) {
        conv_one(A, W, idx);
        conv_one(A, W, idx + HALF4);
    } else if (idx < HALF4 + NROPE) {
        int t = idx - HALF4;
        int l = t >> 5;
        int i = t & 31;
        float invf = exp2f((float)i * -0.41524101186092027f);
        float s, c;
        sincosf((float)l * invf, &s, &c);
        g_sin[t] = s;
        g_cos[t] = c;
    }
}

// ---------------------------------------------------------------------------
// Kernel 1: x = inputs @ W (bf16 wmma), cp.async 2-stage pipeline, BK=64,
// fused bias + RoPE epilogue writing bf16 q/k in (bh,l,d) layout.
// Block tile 128x128 (one head's q|k columns), 8 warps (4x2). Dynamic smem.
// ---------------------------------------------------------------------------
#define G1_AS_STRIDE 72
#define G1_BS_STRIDE 136
#define G1_A_BYTES (128 * G1_AS_STRIDE * 2)                 // 18432
#define G1_STAGE_BYTES (G1_A_BYTES + 64 * G1_BS_STRIDE * 2) // 18432+17408=35840
#define G1_SMEM (2 * G1_STAGE_BYTES)                        // 71680

__global__ __launch_bounds__(256) void gemm1_kernel(const float* __restrict__ bias) {
    extern __shared__ __align__(16) unsigned char smem_raw[];

    const __nv_bfloat16* Abf = reinterpret_cast<const __nv_bfloat16*>(g_abf2);
    const __nv_bfloat16* Wbf = reinterpret_cast<const __nv_bfloat16*>(g_wbf2);

    const int h   = blockIdx.x;
    const int m0  = blockIdx.y * 128;
    const int n0  = h * 128;
    const int tid = threadIdx.x;
    const int warp = tid >> 5;
    const int wm = warp >> 1;            // 0..3
    const int wn = warp & 1;             // 0..1

    // A tile 128x64 bf16 = 1024 uint4: r=idx>>3 (8/row), c=(idx&7)<<3
    // B tile 64x128 bf16 = 1024 uint4: r=idx>>4 (16/row), c=(idx&15)<<3
    auto copy_tile = [&](int kt, int stage) {
        unsigned char* base = smem_raw + stage * G1_STAGE_BYTES;
        __nv_bfloat16 (*As)[G1_AS_STRIDE] = reinterpret_cast<__nv_bfloat16 (*)[G1_AS_STRIDE]>(base);
        __nv_bfloat16 (*Bs)[G1_BS_STRIDE] = reinterpret_cast<__nv_bfloat16 (*)[G1_BS_STRIDE]>(base + G1_A_BYTES);
        int k0 = kt * 64;
        #pragma unroll
        for (int it = 0; it < 4; it++) {
            int idx = tid + it * 256;          // 0..1023
            int ar = idx >> 3;
            int ac = (idx & 7) << 3;
            cp_async16(&As[ar][ac], &Abf[(size_t)(m0 + ar) * HID + k0 + ac]);
            int br = idx >> 4;
            int bc = (idx & 15) << 3;
            cp_async16(&Bs[br][bc], &Wbf[(size_t)(k0 + br) * OUTD + n0 + bc]);
        }
    };

    wmma::fragment<wmma::accumulator, 16, 16, 16, float> acc[2][4];
    #pragma unroll
    for (int i = 0; i < 2; i++)
        #pragma unroll
        for (int j = 0; j < 4; j++)
            wmma::fill_fragment(acc[i][j], 0.0f);

    copy_tile(0, 0);
    cp_async_commit();

    const int NT = HID / 64;    // 12
    for (int kt = 0; kt < NT; kt++) {
        if (kt + 1 < NT) copy_tile(kt + 1, (kt + 1) & 1);
        cp_async_commit();
        cp_async_wait1();
        __syncthreads();

        unsigned char* base = smem_raw + (kt & 1) * G1_STAGE_BYTES;
        __nv_bfloat16 (*As)[G1_AS_STRIDE] = reinterpret_cast<__nv_bfloat16 (*)[G1_AS_STRIDE]>(base);
        __nv_bfloat16 (*Bs)[G1_BS_STRIDE] = reinterpret_cast<__nv_bfloat16 (*)[G1_BS_STRIDE]>(base + G1_A_BYTES);

        #pragma unroll
        for (int kk = 0; kk < 64; kk += 16) {
            wmma::fragment<wmma::matrix_a,16,16,16,__nv_bfloat16,wmma::row_major> af[2];
            wmma::fragment<wmma::matrix_b,16,16,16,__nv_bfloat16,wmma::row_major> bf[4];
            #pragma unroll
            for (int i = 0; i < 2; i++)
                wmma::load_matrix_sync(af[i], &As[wm*32 + i*16][kk], G1_AS_STRIDE);
            #pragma unroll
            for (int j = 0; j < 4; j++)
                wmma::load_matrix_sync(bf[j], &Bs[kk][wn*64 + j*16], G1_BS_STRIDE);
            #pragma unroll
            for (int i = 0; i < 2; i++)
                #pragma unroll
                for (int j = 0; j < 4; j++)
                    wmma::mma_sync(acc[i][j], af[i], bf[j], acc[i][j]);
        }
        __syncthreads();
    }

    // Epilogue: two 64-row passes through Es (aliases smem), bias+RoPE, bf16 out.
    float (*Es)[132] = reinterpret_cast<float (*)[132]>(smem_raw);   // 64x132x4 = 33792 <= 71680
    const int colT = (tid & 63) << 1;           // fixed per thread
    const int iT   = (colT & 63) >> 1;          // fixed pair index within q or k
    const float b1 = __ldg(&bias[n0 + colT]);
    const float b2 = __ldg(&bias[n0 + colT + 1]);

    #pragma unroll
    for (int half = 0; half < 2; half++) {
        __syncthreads();
        if ((wm >> 1) == half) {
            #pragma unroll
            for (int i = 0; i < 2; i++)
                #pragma unroll
                for (int j = 0; j < 4; j++)
                    wmma::store_matrix_sync(&Es[(wm & 1)*32 + i*16][wn*64 + j*16],
                                            acc[i][j], 132, wmma::mem_row_major);
        }
        __syncthreads();

        #pragma unroll
        for (int it = 0; it < 16; it++) {
            int idx = tid + it * 256;            // 0..4095
            int r   = idx >> 6;
            int m = m0 + half * 64 + r;
            int l = m & (L_ - 1);
            float x1 = Es[r][colT]     + b1;
            float x2 = Es[r][colT + 1] + b2;
            float s = g_sin[l * 32 + iT];
            float c = g_cos[l * 32 + iT];
            float o1 = x1 * c - x2 * s;
            float o2 = x1 * s + x2 * c;
            int bh = (m >> 9) * H_ + h;
            __nv_bfloat16* dst = (colT < 64) ? g_q : g_k;
            int d = colT & 63;
            *reinterpret_cast<__nv_bfloat162*>(&dst[((size_t)bh * L_ + l) * D_ + d]) =
                __floats2bfloat162_rn(o1, o2);
        }
    }
}

// ---------------------------------------------------------------------------
// Kernel 2: logits[bh] = (q @ k^T) / 8, causal + padding mask. bf16 wmma.
// 128x128 output tiles, 256 threads (8 warps as 4x2). Dynamic smem (68 KB):
// single-pass epilogue through full 128x132 f32 staging buffer.
// ---------------------------------------------------------------------------
#define AT_SMEM (128 * 132 * 4)    // 67584 (covers 2x 128x72 bf16 load area = 36864)

__global__ __launch_bounds__(256) void attn_kernel(const int* __restrict__ am,
                                                   float* __restrict__ out) {
    const int bh = blockIdx.z;
    const int b  = bh / H_;
    const int tm = blockIdx.y, tn = blockIdx.x;
    const int m0 = tm * 128, n0 = tn * 128;
    float* obase = out + (size_t)bh * L_ * L_;
    const float NEG = __int_as_float(0xFF7FFFFF);  // -FLT_MAX == finfo(f32).min
    const int tid = threadIdx.x;

    if (tm > tn) {   // whole tile causally masked: 128x128 f32 = 4096 float4
        float4 negv = make_float4(NEG, NEG, NEG, NEG);
        #pragma unroll
        for (int it = 0; it < 16; it++) {
            int idx = tid + it * 256;          // 0..4095
            int r = idx >> 5;                  // 32 float4 per row
            int c = (idx & 31) << 2;
            *reinterpret_cast<float4*>(&obase[(size_t)(m0 + r) * L_ + n0 + c]) = negv;
        }
        return;
    }

    extern __shared__ __align__(16) unsigned char smem_raw[];
    __shared__ unsigned char rowv[128];
    __shared__ unsigned char colv[128];
    __nv_bfloat16 (*qs)[72] = reinterpret_cast<__nv_bfloat16 (*)[72]>(smem_raw);            // 128x72x2 = 18432
    __nv_bfloat16 (*ks)[72] = reinterpret_cast<__nv_bfloat16 (*)[72]>(smem_raw + 18432);
    float (*Es)[132]        = reinterpret_cast<float (*)[132]>(smem_raw);                   // 128x132x4

    const int* amb = am + b * L_;
    if (tid < 128)       rowv[tid]       = (unsigned char)(amb[m0 + tid] != 0);
    else                 colv[tid - 128] = (unsigned char)(amb[n0 + tid - 128] != 0);

    const __nv_bfloat16* qb = &g_q[(size_t)bh * L_ * D_];
    const __nv_bfloat16* kb = &g_k[(size_t)bh * L_ * D_];

    // 128 rows x 64 cols bf16 = 1024 uint4 per matrix; 4 per thread each
    #pragma unroll
    for (int it = 0; it < 4; it++) {
        int idx = tid + it * 256;              // 0..1023
        int r = idx >> 3;                      // 8 uint4 per row
        int c = (idx & 7) << 3;
        *reinterpret_cast<uint4*>(&qs[r][c]) =
            *reinterpret_cast<const uint4*>(&qb[(size_t)(m0 + r) * D_ + c]);
        *reinterpret_cast<uint4*>(&ks[r][c]) =
            *reinterpret_cast<const uint4*>(&kb[(size_t)(n0 + r) * D_ + c]);
    }
    __syncthreads();

    const int warp = tid >> 5;
    const int wm = warp >> 1;    // 0..3
    const int wn = warp & 1;     // 0..1

    wmma::fragment<wmma::accumulator, 16, 16, 16, float> acc[2][4];
    #pragma unroll
    for (int i = 0; i < 2; i++)
        #pragma unroll
        for (int j = 0; j < 4; j++)
            wmma::fill_fragment(acc[i][j], 0.0f);

    #pragma unroll
    for (int kk = 0; kk < D_; kk += 16) {
        wmma::fragment<wmma::matrix_a,16,16,16,__nv_bfloat16,wmma::row_major> af[2];
        wmma::fragment<wmma::matrix_b,16,16,16,__nv_bfloat16,wmma::col_major> bf[4];
        #pragma unroll
        for (int i = 0; i < 2; i++)
            wmma::load_matrix_sync(af[i], &qs[wm*32 + i*16][kk], 72);
        #pragma unroll
        for (int j = 0; j < 4; j++)
            wmma::load_matrix_sync(bf[j], &ks[wn*64 + j*16][kk], 72);
        #pragma unroll
        for (int i = 0; i < 2; i++)
            #pragma unroll
            for (int j = 0; j < 4; j++)
                wmma::mma_sync(acc[i][j], af[i], bf[j], acc[i][j]);
    }

    // Single-pass epilogue: stage full 128x128 to Es, then masked float4 writes.
    __syncthreads();
    #pragma unroll
    for (int i = 0; i < 2; i++)
        #pragma unroll
        for (int j = 0; j < 4; j++)
            wmma::store_matrix_sync(&Es[wm*32 + i*16][wn*64 + j*16],
                                    acc[i][j], 132, wmma::mem_row_major);
    __syncthreads();

    // 128 rows x 32 float4 = 4096 / 256 = 16 iterations
    #pragma unroll
    for (int it = 0; it < 16; it++) {
        int f = tid + it * 256;            // 0..4095
        int r = f >> 5;
        int c4 = (f & 31) << 2;
        int m = m0 + r;
        int n = n0 + c4;
        bool rowok = (rowv[r] != 0);
        uchar4 cv = *reinterpret_cast<const uchar4*>(&colv[c4]);
        float4 v;
        float e0 = Es[r][c4+0] * 0.125f;
        float e1 = Es[r][c4+1] * 0.125f;
        float e2 = Es[r][c4+2] * 0.125f;
        float e3 = Es[r][c4+3] * 0.125f;
        v.x = (rowok && cv.x && (m <= n+0)) ? e0 : NEG;
        v.y = (rowok && cv.y && (m <= n+1)) ? e1 : NEG;
        v.z = (rowok && cv.z && (m <= n+2)) ? e2 : NEG;
        v.w = (rowok && cv.w && (m <= n+3)) ? e3 : NEG;
        *reinterpret_cast<float4*>(&obase[(size_t)m * L_ + n]) = v;
    }
}

// ---------------------------------------------------------------------------
extern "C" void kernel_launch(void* const* d_in, const int* in_sizes, int n_in,
                              void* d_out, int out_size) {
    const float* inputs = (const float*)d_in[0];
    const float* W      = (const float*)d_in[1];
    const float* bias   = (const float*)d_in[2];
    const int*   am     = (const int*)d_in[3];
    float* out = (float*)d_out;

    cudaFuncSetAttribute(gemm1_kernel, cudaFuncAttributeMaxDynamicSharedMemorySize, G1_SMEM);
    cudaFuncSetAttribute(attn_kernel,  cudaFuncAttributeMaxDynamicSharedMemorySize, AT_SMEM);

    prep_kernel<<<(HALF4 + NROPE + 255) / 256, 256>>>(inputs, W);
    gemm1_kernel<<<dim3(H_, MROWS / 128), 256, G1_SMEM>>>(bias);
    attn_kernel<<<dim3(L_ / 128, L_ / 128, BHN), 256, AT_SMEM>>>(am, out);
}

// round 7
// speedup vs baseline: 1.0420x; 1.0420x over previous
#include <cuda_runtime.h>
#include <cuda_bf16.h>
#include <mma.h>
#include <cstdint>

using namespace nvcuda;

#define B_    8
#define L_    512
#define H_    12
#define D_    64
#define HID   768
#define OUTD  1536
#define MROWS 4096          // B_*L_
#define BHN   96            // B_*H_

#define NA4   (MROWS * HID / 4)     // 786432 float4 units of A
#define NW4   (HID * OUTD / 4)      // 294912 float4 units of W
#define NCV4  (NA4 + NW4)           // 1081344
#define QTR4  (NCV4 / 4)            //  270336
#define NROPE (L_ * 32)             //   16384

// Scratch (device globals — no runtime allocation allowed)
__device__ __nv_bfloat162 g_abf2[MROWS * HID / 2];
__device__ __nv_bfloat162 g_wbf2[HID * OUTD / 2];
__device__ __nv_bfloat16  g_q[BHN * L_ * D_];   // q, (bh, l, d) bf16
__device__ __nv_bfloat16  g_k[BHN * L_ * D_];   // k, (bh, l, d) bf16
__device__ float          g_sin[NROPE];
__device__ float          g_cos[NROPE];

// Upper-triangular 128x128 tile list (tm, tn), tn >= tm, 4x4 grid
__device__ const signed char UP_TM[10] = {0,0,0,0,1,1,1,2,2,3};
__device__ const signed char UP_TN[10] = {0,1,2,3,1,2,3,2,3,3};
// Below-diagonal tiles
__device__ const signed char FL_TM[6] = {1,2,2,3,3,3};
__device__ const signed char FL_TN[6] = {0,0,1,0,1,2};

static __device__ __forceinline__ void cp_async16(void* smem_dst, const void* gmem_src) {
    unsigned saddr = (unsigned)__cvta_generic_to_shared(smem_dst);
    asm volatile("cp.async.cg.shared.global [%0], [%1], 16;\n" :: "r"(saddr), "l"(gmem_src));
}
static __device__ __forceinline__ void cp_async_commit() {
    asm volatile("cp.async.commit_group;\n" ::: "memory");
}
static __device__ __forceinline__ void cp_async_wait2() {
    asm volatile("cp.async.wait_group 2;\n" ::: "memory");
}

// ---------------------------------------------------------------------------
// Kernel 0: convert inputs/W to bf16 + RoPE tables. 4 float4 per thread (MLP).
// ---------------------------------------------------------------------------
static __device__ __forceinline__ void conv_one(const float* __restrict__ A,
                                                const float* __restrict__ W, int j) {
    if (j < NA4) {
        float4 v = reinterpret_cast<const float4*>(A)[j];
        __nv_bfloat162 lo = __floats2bfloat162_rn(v.x, v.y);
        __nv_bfloat162 hi = __floats2bfloat162_rn(v.z, v.w);
        reinterpret_cast<uint2*>(g_abf2)[j] =
            make_uint2(*reinterpret_cast<unsigned*>(&lo), *reinterpret_cast<unsigned*>(&hi));
    } else {
        int t = j - NA4;
        float4 v = reinterpret_cast<const float4*>(W)[t];
        __nv_bfloat162 lo = __floats2bfloat162_rn(v.x, v.y);
        __nv_bfloat162 hi = __floats2bfloat162_rn(v.z, v.w);
        reinterpret_cast<uint2*>(g_wbf2)[t] =
            make_uint2(*reinterpret_cast<unsigned*>(&lo), *reinterpret_cast<unsigned*>(&hi));
    }
}

__global__ __launch_bounds__(256) void prep_kernel(const float* __restrict__ A,
                                                   const float* __restrict__ W) {
    int idx = blockIdx.x * 256 + threadIdx.x;
    if (idx < QTR4) {
        conv_one(A, W, idx);
        conv_one(A, W, idx + QTR4);
        conv_one(A, W, idx + 2 * QTR4);
        conv_one(A, W, idx + 3 * QTR4);
    } else if (idx < QTR4 + NROPE) {
        int t = idx - QTR4;
        int l = t >> 5;
        int i = t & 31;
        float invf = exp2f((float)i * -0.41524101186092027f);
        float s, c;
        sincosf((float)l * invf, &s, &c);
        g_sin[t] = s;
        g_cos[t] = c;
    }
}

// ---------------------------------------------------------------------------
// Kernel 1: x = inputs @ W (bf16 wmma), cp.async 3-stage pipeline (BK=32),
// fused bias + RoPE epilogue writing bf16 q/k in (bh,l,d) layout.
// Block tile 128x128 (one head's q|k columns), 8 warps (4x2). Dynamic smem.
// ---------------------------------------------------------------------------
#define G1_AS_STRIDE 40
#define G1_BS_STRIDE 136
#define G1_A_BYTES (128 * G1_AS_STRIDE * 2)                 // 10240
#define G1_STAGE_BYTES (G1_A_BYTES + 32 * G1_BS_STRIDE * 2) // 10240+8704=18944
#define G1_SMEM (3 * G1_STAGE_BYTES)                        // 56832

__global__ __launch_bounds__(256) void gemm1_kernel(const float* __restrict__ bias) {
    extern __shared__ __align__(16) unsigned char smem_raw[];

    const __nv_bfloat16* Abf = reinterpret_cast<const __nv_bfloat16*>(g_abf2);
    const __nv_bfloat16* Wbf = reinterpret_cast<const __nv_bfloat16*>(g_wbf2);

    const int h   = blockIdx.x;
    const int m0  = blockIdx.y * 128;
    const int n0  = h * 128;
    const int tid = threadIdx.x;
    const int warp = tid >> 5;
    const int wm = warp >> 1;            // 0..3
    const int wn = warp & 1;             // 0..1

    // A tile 128x32 bf16 = 512 uint4: r=idx>>2 (4/row), c=(idx&3)<<3
    // B tile 32x128 bf16 = 512 uint4: r=idx>>4 (16/row), c=(idx&15)<<3
    auto copy_tile = [&](int kt) {
        unsigned char* base = smem_raw + (kt % 3) * G1_STAGE_BYTES;
        __nv_bfloat16 (*As)[G1_AS_STRIDE] = reinterpret_cast<__nv_bfloat16 (*)[G1_AS_STRIDE]>(base);
        __nv_bfloat16 (*Bs)[G1_BS_STRIDE] = reinterpret_cast<__nv_bfloat16 (*)[G1_BS_STRIDE]>(base + G1_A_BYTES);
        int k0 = kt * 32;
        #pragma unroll
        for (int it = 0; it < 2; it++) {
            int idx = tid + it * 256;          // 0..511
            int ar = idx >> 2;
            int ac = (idx & 3) << 3;
            cp_async16(&As[ar][ac], &Abf[(size_t)(m0 + ar) * HID + k0 + ac]);
            int br = idx >> 4;
            int bc = (idx & 15) << 3;
            cp_async16(&Bs[br][bc], &Wbf[(size_t)(k0 + br) * OUTD + n0 + bc]);
        }
    };

    wmma::fragment<wmma::accumulator, 16, 16, 16, float> acc[2][4];
    #pragma unroll
    for (int i = 0; i < 2; i++)
        #pragma unroll
        for (int j = 0; j < 4; j++)
            wmma::fill_fragment(acc[i][j], 0.0f);

    copy_tile(0);
    cp_async_commit();
    copy_tile(1);
    cp_async_commit();

    const int NT = HID / 32;    // 24
    for (int kt = 0; kt < NT; kt++) {
        if (kt + 2 < NT) copy_tile(kt + 2);
        cp_async_commit();
        cp_async_wait2();       // stage kt complete
        __syncthreads();

        unsigned char* base = smem_raw + (kt % 3) * G1_STAGE_BYTES;
        __nv_bfloat16 (*As)[G1_AS_STRIDE] = reinterpret_cast<__nv_bfloat16 (*)[G1_AS_STRIDE]>(base);
        __nv_bfloat16 (*Bs)[G1_BS_STRIDE] = reinterpret_cast<__nv_bfloat16 (*)[G1_BS_STRIDE]>(base + G1_A_BYTES);

        #pragma unroll
        for (int kk = 0; kk < 32; kk += 16) {
            wmma::fragment<wmma::matrix_a,16,16,16,__nv_bfloat16,wmma::row_major> af[2];
            wmma::fragment<wmma::matrix_b,16,16,16,__nv_bfloat16,wmma::row_major> bf[4];
            #pragma unroll
            for (int i = 0; i < 2; i++)
                wmma::load_matrix_sync(af[i], &As[wm*32 + i*16][kk], G1_AS_STRIDE);
            #pragma unroll
            for (int j = 0; j < 4; j++)
                wmma::load_matrix_sync(bf[j], &Bs[kk][wn*64 + j*16], G1_BS_STRIDE);
            #pragma unroll
            for (int i = 0; i < 2; i++)
                #pragma unroll
                for (int j = 0; j < 4; j++)
                    wmma::mma_sync(acc[i][j], af[i], bf[j], acc[i][j]);
        }
        __syncthreads();
    }

    // Epilogue: two 64-row passes through Es (aliases smem), bias+RoPE, bf16 out.
    float (*Es)[132] = reinterpret_cast<float (*)[132]>(smem_raw);   // 64x132x4 = 33792 <= 56832
    const int colT = (tid & 63) << 1;           // fixed per thread
    const int iT   = (colT & 63) >> 1;          // fixed pair index within q or k
    const float b1 = __ldg(&bias[n0 + colT]);
    const float b2 = __ldg(&bias[n0 + colT + 1]);

    #pragma unroll
    for (int half = 0; half < 2; half++) {
        __syncthreads();
        if ((wm >> 1) == half) {
            #pragma unroll
            for (int i = 0; i < 2; i++)
                #pragma unroll
                for (int j = 0; j < 4; j++)
                    wmma::store_matrix_sync(&Es[(wm & 1)*32 + i*16][wn*64 + j*16],
                                            acc[i][j], 132, wmma::mem_row_major);
        }
        __syncthreads();

        #pragma unroll
        for (int it = 0; it < 16; it++) {
            int idx = tid + it * 256;            // 0..4095
            int r   = idx >> 6;
            int m = m0 + half * 64 + r;
            int l = m & (L_ - 1);
            float x1 = Es[r][colT]     + b1;
            float x2 = Es[r][colT + 1] + b2;
            float s = g_sin[l * 32 + iT];
            float c = g_cos[l * 32 + iT];
            float o1 = x1 * c - x2 * s;
            float o2 = x1 * s + x2 * c;
            int bh = (m >> 9) * H_ + h;
            __nv_bfloat16* dst = (colT < 64) ? g_q : g_k;
            int d = colT & 63;
            *reinterpret_cast<__nv_bfloat162*>(&dst[((size_t)bh * L_ + l) * D_ + d]) =
                __floats2bfloat162_rn(o1, o2);
        }
    }
}

// ---------------------------------------------------------------------------
// Kernel 2a: fill below-diagonal 128x128 tiles with -FLT_MAX. Pure streaming.
// ---------------------------------------------------------------------------
__global__ __launch_bounds__(256) void fill_kernel(float* __restrict__ out) {
    const int bh = blockIdx.y;
    const int m0 = (int)FL_TM[blockIdx.x] * 128;
    const int n0 = (int)FL_TN[blockIdx.x] * 128;
    float* obase = out + (size_t)bh * L_ * L_;
    const float NEG = __int_as_float(0xFF7FFFFF);
    const int tid = threadIdx.x;
    float4 negv = make_float4(NEG, NEG, NEG, NEG);
    #pragma unroll
    for (int it = 0; it < 16; it++) {
        int idx = tid + it * 256;          // 0..4095
        int r = idx >> 5;                  // 32 float4 per row
        int c = (idx & 31) << 2;
        *reinterpret_cast<float4*>(&obase[(size_t)(m0 + r) * L_ + n0 + c]) = negv;
    }
}

// ---------------------------------------------------------------------------
// Kernel 2b: logits[bh] = (q @ k^T) / 8 on upper-triangular tiles only.
// bf16 wmma, 128x128 tiles, 256 threads (8 warps as 4x2), static smem.
// Mask flags staged in smem; two 64-row epilogue passes.
// ---------------------------------------------------------------------------
__global__ __launch_bounds__(256) void attn_kernel(const int* __restrict__ am,
                                                   float* __restrict__ out) {
    const int bh = blockIdx.y;
    const int b  = bh / H_;
    const int m0 = (int)UP_TM[blockIdx.x] * 128;
    const int n0 = (int)UP_TN[blockIdx.x] * 128;
    float* obase = out + (size_t)bh * L_ * L_;
    const float NEG = __int_as_float(0xFF7FFFFF);  // -FLT_MAX == finfo(f32).min
    const int tid = threadIdx.x;

    __shared__ __align__(16) unsigned char smem_raw[36864];
    __shared__ unsigned char rowv[128];
    __shared__ unsigned char colv[128];
    __nv_bfloat16 (*qs)[72] = reinterpret_cast<__nv_bfloat16 (*)[72]>(smem_raw);            // 128x72x2 = 18432
    __nv_bfloat16 (*ks)[72] = reinterpret_cast<__nv_bfloat16 (*)[72]>(smem_raw + 18432);
    float (*Es)[132]        = reinterpret_cast<float (*)[132]>(smem_raw);                   // 64x132x4 = 33792

    const int* amb = am + b * L_;
    if (tid < 128)       rowv[tid]       = (unsigned char)(amb[m0 + tid] != 0);
    else                 colv[tid - 128] = (unsigned char)(amb[n0 + tid - 128] != 0);

    const __nv_bfloat16* qb = &g_q[(size_t)bh * L_ * D_];
    const __nv_bfloat16* kb = &g_k[(size_t)bh * L_ * D_];

    // 128 rows x 64 cols bf16 = 1024 uint4 per matrix; 4 per thread each
    #pragma unroll
    for (int it = 0; it < 4; it++) {
        int idx = tid + it * 256;              // 0..1023
        int r = idx >> 3;                      // 8 uint4 per row
        int c = (idx & 7) << 3;
        *reinterpret_cast<uint4*>(&qs[r][c]) =
            *reinterpret_cast<const uint4*>(&qb[(size_t)(m0 + r) * D_ + c]);
        *reinterpret_cast<uint4*>(&ks[r][c]) =
            *reinterpret_cast<const uint4*>(&kb[(size_t)(n0 + r) * D_ + c]);
    }
    __syncthreads();

    const int warp = tid >> 5;
    const int wm = warp >> 1;    // 0..3
    const int wn = warp & 1;     // 0..1

    wmma::fragment<wmma::accumulator, 16, 16, 16, float> acc[2][4];
    #pragma unroll
    for (int i = 0; i < 2; i++)
        #pragma unroll
        for (int j = 0; j < 4; j++)
            wmma::fill_fragment(acc[i][j], 0.0f);

    #pragma unroll
    for (int kk = 0; kk < D_; kk += 16) {
        wmma::fragment<wmma::matrix_a,16,16,16,__nv_bfloat16,wmma::row_major> af[2];
        wmma::fragment<wmma::matrix_b,16,16,16,__nv_bfloat16,wmma::col_major> bf[4];
        #pragma unroll
        for (int i = 0; i < 2; i++)
            wmma::load_matrix_sync(af[i], &qs[wm*32 + i*16][kk], 72);
        #pragma unroll
        for (int j = 0; j < 4; j++)
            wmma::load_matrix_sync(bf[j], &ks[wn*64 + j*16][kk], 72);
        #pragma unroll
        for (int i = 0; i < 2; i++)
            #pragma unroll
            for (int j = 0; j < 4; j++)
                wmma::mma_sync(acc[i][j], af[i], bf[j], acc[i][j]);
    }

    // Two 64-row passes: stage to Es (aliases qs/ks), masked float4 writes.
    #pragma unroll
    for (int half = 0; half < 2; half++) {
        __syncthreads();
        if ((wm >> 1) == half) {
            #pragma unroll
            for (int i = 0; i < 2; i++)
                #pragma unroll
                for (int j = 0; j < 4; j++)
                    wmma::store_matrix_sync(&Es[(wm & 1)*32 + i*16][wn*64 + j*16],
                                            acc[i][j], 132, wmma::mem_row_major);
        }
        __syncthreads();

        // 64 rows x 32 float4 = 2048 / 256 = 8 iterations
        #pragma unroll
        for (int it = 0; it < 8; it++) {
            int f = tid + it * 256;            // 0..2047
            int r = f >> 5;
            int c4 = (f & 31) << 2;
            int m = m0 + half * 64 + r;
            int n = n0 + c4;
            bool rowok = (rowv[half * 64 + r] != 0);
            uchar4 cv = *reinterpret_cast<const uchar4*>(&colv[c4]);
            float4 v;
            float e0 = Es[r][c4+0] * 0.125f;
            float e1 = Es[r][c4+1] * 0.125f;
            float e2 = Es[r][c4+2] * 0.125f;
            float e3 = Es[r][c4+3] * 0.125f;
            v.x = (rowok && cv.x && (m <= n+0)) ? e0 : NEG;
            v.y = (rowok && cv.y && (m <= n+1)) ? e1 : NEG;
            v.z = (rowok && cv.z && (m <= n+2)) ? e2 : NEG;
            v.w = (rowok && cv.w && (m <= n+3)) ? e3 : NEG;
            *reinterpret_cast<float4*>(&obase[(size_t)m * L_ + n]) = v;
        }
    }
}

// ---------------------------------------------------------------------------
extern "C" void kernel_launch(void* const* d_in, const int* in_sizes, int n_in,
                              void* d_out, int out_size) {
    const float* inputs = (const float*)d_in[0];
    const float* W      = (const float*)d_in[1];
    const float* bias   = (const float*)d_in[2];
    const int*   am     = (const int*)d_in[3];
    float* out = (float*)d_out;

    cudaFuncSetAttribute(gemm1_kernel, cudaFuncAttributeMaxDynamicSharedMemorySize, G1_SMEM);

    prep_kernel<<<(QTR4 + NROPE + 255) / 256, 256>>>(inputs, W);
    gemm1_kernel<<<dim3(H_, MROWS / 128), 256, G1_SMEM>>>(bias);
    fill_kernel<<<dim3(6, BHN), 256>>>(out);
    attn_kernel<<<dim3(10, BHN), 256>>>(am, out);
}

// round 10
// speedup vs baseline: 1.1140x; 1.0691x over previous
#include <cuda_runtime.h>
#include <cuda_bf16.h>
#include <cstdint>

#define B_    8
#define L_    512
#define H_    12
#define D_    64
#define HID   768
#define OUTD  1536
#define MROWS 4096          // B_*L_
#define BHN   96            // B_*H_

#define NA4   (MROWS * HID / 4)     // 786432 float4 units of A
#define NAQ   (NA4 / 4)             // 196608
#define NROPE (L_ * 32)             //  16384

// Scratch (device globals — no runtime allocation allowed)
__device__ __nv_bfloat16 g_abf[MROWS * HID];    // inputs bf16 [4096 x 768]
__device__ __nv_bfloat16 g_wt[OUTD * HID];      // W^T bf16 [1536 x 768] K-major
__device__ __nv_bfloat16 g_q[BHN * L_ * D_];    // q, (bh, l, d) bf16
__device__ __nv_bfloat16 g_k[BHN * L_ * D_];    // k, (bh, l, d) bf16
__device__ float         g_sin[NROPE];
__device__ float         g_cos[NROPE];

// Upper-triangular 128x128 tile list (tm, tn), tn >= tm, 4x4 grid
__device__ const signed char UP_TM[10] = {0,0,0,0,1,1,1,2,2,3};
__device__ const signed char UP_TN[10] = {0,1,2,3,1,2,3,2,3,3};
// Below-diagonal tiles
__device__ const signed char FL_TM[6] = {1,2,2,3,3,3};
__device__ const signed char FL_TN[6] = {0,0,1,0,1,2};

// ---------------------------------------------------------------------------
// PTX helpers
// ---------------------------------------------------------------------------
static __device__ __forceinline__ uint32_t smem_u32(const void* p) {
    uint32_t a;
    asm("{ .reg .u64 t; cvta.to.shared.u64 t, %1; cvt.u32.u64 %0, t; }" : "=r"(a) : "l"(p));
    return a;
}
static __device__ __forceinline__ void cp_async16_s(uint32_t saddr, const void* g) {
    asm volatile("cp.async.cg.shared.global [%0], [%1], 16;\n" :: "r"(saddr), "l"(g));
}
static __device__ __forceinline__ void cp_commit() {
    asm volatile("cp.async.commit_group;\n" ::: "memory");
}
static __device__ __forceinline__ void ldsm_x4(uint32_t* r, uint32_t addr) {
    asm volatile("ldmatrix.sync.aligned.m8n8.x4.shared.b16 {%0,%1,%2,%3}, [%4];"
                 : "=r"(r[0]), "=r"(r[1]), "=r"(r[2]), "=r"(r[3]) : "r"(addr));
}
static __device__ __forceinline__ void ldsm_x2(uint32_t* r, uint32_t addr) {
    asm volatile("ldmatrix.sync.aligned.m8n8.x2.shared.b16 {%0,%1}, [%2];"
                 : "=r"(r[0]), "=r"(r[1]) : "r"(addr));
}
static __device__ __forceinline__ void mma16816(float* d, const uint32_t* a, const uint32_t* b) {
    asm volatile(
        "mma.sync.aligned.m16n8k16.row.col.f32.bf16.bf16.f32 "
        "{%0,%1,%2,%3}, {%4,%5,%6,%7}, {%8,%9}, {%0,%1,%2,%3};"
        : "+f"(d[0]), "+f"(d[1]), "+f"(d[2]), "+f"(d[3])
        : "r"(a[0]), "r"(a[1]), "r"(a[2]), "r"(a[3]), "r"(b[0]), "r"(b[1]));
}

// ---------------------------------------------------------------------------
// Kernel 0: convert inputs to bf16 + RoPE tables.
// ---------------------------------------------------------------------------
static __device__ __forceinline__ void conv_a(const float* __restrict__ A, int j) {
    float4 v = reinterpret_cast<const float4*>(A)[j];
    __nv_bfloat162 lo = __floats2bfloat162_rn(v.x, v.y);
    __nv_bfloat162 hi = __floats2bfloat162_rn(v.z, v.w);
    reinterpret_cast<uint2*>(g_abf)[j] =
        make_uint2(*reinterpret_cast<unsigned*>(&lo), *reinterpret_cast<unsigned*>(&hi));
}

__global__ __launch_bounds__(256) void prep_kernel(const float* __restrict__ A) {
    int idx = blockIdx.x * 256 + threadIdx.x;
    if (idx < NAQ) {
        conv_a(A, idx);
        conv_a(A, idx + NAQ);
        conv_a(A, idx + 2 * NAQ);
        conv_a(A, idx + 3 * NAQ);
    } else if (idx < NAQ + NROPE) {
        int t = idx - NAQ;
        int l = t >> 5;
        int i = t & 31;
        float invf = exp2f((float)i * -0.41524101186092027f);
        float s, c;
        sincosf((float)l * invf, &s, &c);
        g_sin[t] = s;
        g_cos[t] = c;
    }
}

// ---------------------------------------------------------------------------
// Kernel 0b: W [768 x 1536] f32 -> g_wt [1536 x 768] bf16 (tiled transpose)
// ---------------------------------------------------------------------------
__global__ __launch_bounds__(256) void wtrans_kernel(const float* __restrict__ W) {
    __shared__ float t[32][33];
    int n0 = blockIdx.x * 32, k0 = blockIdx.y * 32;
    int tx = threadIdx.x & 31, ty = threadIdx.x >> 5;   // 32x8
    #pragma unroll
    for (int i = 0; i < 4; i++)
        t[ty + i*8][tx] = W[(size_t)(k0 + ty + i*8) * OUTD + n0 + tx];
    __syncthreads();
    #pragma unroll
    for (int i = 0; i < 4; i++)
        g_wt[(size_t)(n0 + ty + i*8) * HID + k0 + tx] = __float2bfloat16(t[tx][ty + i*8]);
}

// ---------------------------------------------------------------------------
// Kernel 1: x = inputs @ W via mma.sync, bias+RoPE in registers, bf16 q/k out.
// Block 128m x 128n (one head), 8 warps (4x2), warp 32x64.
// BK=32, 3-stage cp.async pipeline. Both operands K-major rows (stride 80B).
// ---------------------------------------------------------------------------
#define G1_ROWB   80                        // bytes per smem row (32 bf16 + pad)
#define G1_OPB    (128 * G1_ROWB)           // 10240 per operand
#define G1_STAGE  (2 * G1_OPB)              // 20480
#define G1_SMEM   (3 * G1_STAGE)            // 61440

__global__ __launch_bounds__(256, 2) void gemm1_kernel(const float* __restrict__ bias) {
    extern __shared__ __align__(16) unsigned char dsm[];
    __shared__ float bias_s[128];

    const int tid  = threadIdx.x;
    const int lane = tid & 31;
    const int w    = tid >> 5;
    const int wm   = w >> 1;             // 0..3
    const int wn   = w & 1;              // 0..1
    const int h    = blockIdx.x;
    const int m0   = blockIdx.y * 128;
    const int n0   = h * 128;

    if (tid < 128) bias_s[tid] = __ldg(&bias[n0 + tid]);

    const uint32_t sbase = smem_u32(dsm);

    // copy one BK=32 stage: A rows [m0..+128), B rows (g_wt) [n0..+128)
    auto copy_stage = [&](int kt) {
        uint32_t base = sbase + (kt % 3) * G1_STAGE;
        int k0e = kt * 32;
        #pragma unroll
        for (int it = 0; it < 4; it++) {
            int idx = tid + it * 256;            // 0..1023
            int r = (idx >> 2) & 127;
            int c = idx & 3;                     // 16B chunk
            if (idx < 512)
                cp_async16_s(base + r * G1_ROWB + c * 16,
                             &g_abf[(size_t)(m0 + r) * HID + k0e + c * 8]);
            else
                cp_async16_s(base + G1_OPB + r * G1_ROWB + c * 16,
                             &g_wt[(size_t)(n0 + r) * HID + k0e + c * 8]);
        }
    };

    // per-thread ldmatrix address offsets (relative to stage base)
    uint32_t a_off[2], b_off[8];
    #pragma unroll
    for (int mi = 0; mi < 2; mi++)
        a_off[mi] = (uint32_t)((wm*32 + mi*16 + (lane & 15)) * G1_ROWB + ((lane >> 4) * 16));
    #pragma unroll
    for (int nj = 0; nj < 8; nj++)
        b_off[nj] = (uint32_t)(G1_OPB + (wn*64 + nj*8 + (lane & 7)) * G1_ROWB + (((lane >> 3) & 1) * 16));

    float acc[2][8][4];
    #pragma unroll
    for (int mi = 0; mi < 2; mi++)
        #pragma unroll
        for (int nj = 0; nj < 8; nj++)
            #pragma unroll
            for (int x = 0; x < 4; x++)
                acc[mi][nj][x] = 0.0f;

    copy_stage(0); cp_commit();
    copy_stage(1); cp_commit();

    const int NT = HID / 32;   // 24
    for (int kt = 0; kt < NT; kt++) {
        if (kt + 2 < NT) {
            copy_stage(kt + 2); cp_commit();
            asm volatile("cp.async.wait_group 2;" ::: "memory");
        } else if (kt + 1 < NT) {
            asm volatile("cp.async.wait_group 1;" ::: "memory");
        } else {
            asm volatile("cp.async.wait_group 0;" ::: "memory");
        }
        __syncthreads();

        uint32_t stg = sbase + (kt % 3) * G1_STAGE;
        #pragma unroll
        for (int ks = 0; ks < 2; ks++) {         // two k16 steps per BK=32
            uint32_t koff = ks * 32;             // 16 halfwords = 32B
            uint32_t a[2][4], b[8][2];
            #pragma unroll
            for (int mi = 0; mi < 2; mi++)
                ldsm_x4(a[mi], stg + a_off[mi] + koff);
            #pragma unroll
            for (int nj = 0; nj < 8; nj++)
                ldsm_x2(b[nj], stg + b_off[nj] + koff);
            #pragma unroll
            for (int mi = 0; mi < 2; mi++)
                #pragma unroll
                for (int nj = 0; nj < 8; nj++)
                    mma16816(acc[mi][nj], a[mi], b[nj]);
        }
        __syncthreads();
    }

    // Epilogue: bias + RoPE in registers, store bf16x2 to g_q / g_k.
    __nv_bfloat16* dst = wn ? g_k : g_q;
    float bv[8][2];
    #pragma unroll
    for (int nj = 0; nj < 8; nj++) {
        int nl = wn*64 + nj*8 + (lane & 3) * 2;
        bv[nj][0] = bias_s[nl];
        bv[nj][1] = bias_s[nl + 1];
    }

    #pragma unroll
    for (int mi = 0; mi < 2; mi++) {
        #pragma unroll
        for (int rh = 0; rh < 2; rh++) {
            int m_g = m0 + wm*32 + mi*16 + (lane >> 2) + rh*8;
            int l = m_g & (L_ - 1);
            int bidx = m_g >> 9;
            size_t rowp = ((size_t)(bidx * H_ + h) * L_ + l) * D_;
            #pragma unroll
            for (int nj = 0; nj < 8; nj++) {
                float x1 = acc[mi][nj][rh*2 + 0] + bv[nj][0];
                float x2 = acc[mi][nj][rh*2 + 1] + bv[nj][1];
                int i = nj*4 + (lane & 3);
                float s = g_sin[l * 32 + i];
                float c = g_cos[l * 32 + i];
                __nv_bfloat162 pr = __floats2bfloat162_rn(x1 * c - x2 * s, x1 * s + x2 * c);
                int d = nj*8 + (lane & 3) * 2;
                *reinterpret_cast<uint32_t*>(&dst[rowp + d]) = *reinterpret_cast<uint32_t*>(&pr);
            }
        }
    }
}

// ---------------------------------------------------------------------------
// Kernel 2a: fill below-diagonal 128x128 tiles with -FLT_MAX. Pure streaming.
// ---------------------------------------------------------------------------
__global__ __launch_bounds__(256) void fill_kernel(float* __restrict__ out) {
    const int bh = blockIdx.y;
    const int m0 = (int)FL_TM[blockIdx.x] * 128;
    const int n0 = (int)FL_TN[blockIdx.x] * 128;
    float* obase = out + (size_t)bh * L_ * L_;
    const float NEG = __int_as_float(0xFF7FFFFF);
    const int tid = threadIdx.x;
    float4 negv = make_float4(NEG, NEG, NEG, NEG);
    #pragma unroll
    for (int it = 0; it < 16; it++) {
        int idx = tid + it * 256;          // 0..4095
        int r = idx >> 5;
        int c = (idx & 31) << 2;
        *reinterpret_cast<float4*>(&obase[(size_t)(m0 + r) * L_ + n0 + c]) = negv;
    }
}

// ---------------------------------------------------------------------------
// Kernel 2b: logits = (q @ k^T)/8 on upper-triangular tiles via mma.sync.
// Masks applied in registers, float2 stores. 128x128 tile, 8 warps (4x2).
// ---------------------------------------------------------------------------
#define AT_ROWB 144    // 64 bf16 (128B) + 16B pad

__global__ __launch_bounds__(256, 2) void attn_kernel(const int* __restrict__ am,
                                                      float* __restrict__ out) {
    const int bh = blockIdx.y;
    const int b  = bh / H_;
    const int m0 = (int)UP_TM[blockIdx.x] * 128;
    const int n0 = (int)UP_TN[blockIdx.x] * 128;
    float* obase = out + (size_t)bh * L_ * L_;
    const float NEG = __int_as_float(0xFF7FFFFF);  // -FLT_MAX == finfo(f32).min
    const int tid  = threadIdx.x;
    const int lane = tid & 31;
    const int w    = tid >> 5;
    const int wm   = w >> 1;
    const int wn   = w & 1;

    __shared__ __align__(16) unsigned char qmem[128 * AT_ROWB];
    __shared__ __align__(16) unsigned char kmem[128 * AT_ROWB];
    __shared__ unsigned char rowv[128];
    __shared__ unsigned char colv[128];

    const int* amb = am + b * L_;
    if (tid < 128)       rowv[tid]       = (unsigned char)(amb[m0 + tid] != 0);
    else                 colv[tid - 128] = (unsigned char)(amb[n0 + tid - 128] != 0);

    const __nv_bfloat16* qb = &g_q[(size_t)bh * L_ * D_];
    const __nv_bfloat16* kb = &g_k[(size_t)bh * L_ * D_];

    // 128 rows x 64 cols bf16 = 128B per row = 8 uint4; 1024 uint4 per matrix
    #pragma unroll
    for (int it = 0; it < 4; it++) {
        int idx = tid + it * 256;              // 0..1023
        int r = idx >> 3;
        int c = (idx & 7) << 4;                // byte offset within row
        const unsigned char* qsrc = reinterpret_cast<const unsigned char*>(qb + (size_t)(m0 + r) * D_);
        const unsigned char* ksrc = reinterpret_cast<const unsigned char*>(kb + (size_t)(n0 + r) * D_);
        *reinterpret_cast<uint4*>(qmem + r * AT_ROWB + c) =
            *reinterpret_cast<const uint4*>(qsrc + c);
        *reinterpret_cast<uint4*>(kmem + r * AT_ROWB + c) =
            *reinterpret_cast<const uint4*>(ksrc + c);
    }
    __syncthreads();

    const uint32_t qbase = smem_u32(qmem);
    const uint32_t kbase = smem_u32(kmem);

    uint32_t a_off[2], b_off[8];
    #pragma unroll
    for (int mi = 0; mi < 2; mi++)
        a_off[mi] = qbase + (uint32_t)((wm*32 + mi*16 + (lane & 15)) * AT_ROWB + ((lane >> 4) * 16));
    #pragma unroll
    for (int nj = 0; nj < 8; nj++)
        b_off[nj] = kbase + (uint32_t)((wn*64 + nj*8 + (lane & 7)) * AT_ROWB + (((lane >> 3) & 1) * 16));

    float acc[2][8][4];
    #pragma unroll
    for (int mi = 0; mi < 2; mi++)
        #pragma unroll
        for (int nj = 0; nj < 8; nj++)
            #pragma unroll
            for (int x = 0; x < 4; x++)
                acc[mi][nj][x] = 0.0f;

    #pragma unroll
    for (int ks = 0; ks < 4; ks++) {           // D=64 -> 4 k16 steps
        uint32_t koff = ks * 32;               // 16 halfwords
        uint32_t a[2][4], bfr[8][2];
        #pragma unroll
        for (int mi = 0; mi < 2; mi++)
            ldsm_x4(a[mi], a_off[mi] + koff);
        #pragma unroll
        for (int nj = 0; nj < 8; nj++)
            ldsm_x2(bfr[nj], b_off[nj] + koff);
        #pragma unroll
        for (int mi = 0; mi < 2; mi++)
            #pragma unroll
            for (int nj = 0; nj < 8; nj++)
                mma16816(acc[mi][nj], a[mi], bfr[nj]);
    }

    // Masked register epilogue: float2 stores.
    #pragma unroll
    for (int mi = 0; mi < 2; mi++) {
        #pragma unroll
        for (int rh = 0; rh < 2; rh++) {
            int r_loc = wm*32 + mi*16 + (lane >> 2) + rh*8;
            int m = m0 + r_loc;
            bool rowok = (rowv[r_loc] != 0);
            #pragma unroll
            for (int nj = 0; nj < 8; nj++) {
                int n_loc = wn*64 + nj*8 + (lane & 3) * 2;
                int n = n0 + n_loc;
                float e0 = acc[mi][nj][rh*2 + 0] * 0.125f;
                float e1 = acc[mi][nj][rh*2 + 1] * 0.125f;
                bool v0 = rowok && colv[n_loc]     && (m <= n);
                bool v1 = rowok && colv[n_loc + 1] && (m <= n + 1);
                float2 val;
                val.x = v0 ? e0 : NEG;
                val.y = v1 ? e1 : NEG;
                *reinterpret_cast<float2*>(&obase[(size_t)m * L_ + n]) = val;
            }
        }
    }
}

// ---------------------------------------------------------------------------
extern "C" void kernel_launch(void* const* d_in, const int* in_sizes, int n_in,
                              void* d_out, int out_size) {
    const float* inputs = (const float*)d_in[0];
    const float* W      = (const float*)d_in[1];
    const float* bias   = (const float*)d_in[2];
    const int*   am     = (const int*)d_in[3];
    float* out = (float*)d_out;

    cudaFuncSetAttribute(gemm1_kernel, cudaFuncAttributeMaxDynamicSharedMemorySize, G1_SMEM);

    prep_kernel<<<(NAQ + NROPE + 255) / 256, 256>>>(inputs);
    wtrans_kernel<<<dim3(OUTD / 32, HID / 32), 256>>>(W);
    gemm1_kernel<<<dim3(H_, MROWS / 128), 256, G1_SMEM>>>(bias);
    fill_kernel<<<dim3(6, BHN), 256>>>(out);
    attn_kernel<<<dim3(10, BHN), 256>>>(am, out);
}

// round 11
// speedup vs baseline: 1.1444x; 1.0273x over previous
#include <cuda_runtime.h>
#include <cuda_bf16.h>
#include <cstdint>

#define B_    8
#define L_    512
#define H_    12
#define D_    64
#define HID   768
#define OUTD  1536
#define MROWS 4096          // B_*L_
#define BHN   96            // B_*H_

#define NA4   (MROWS * HID / 4)     // 786432 float4 units of A
#define NAQ   (NA4 / 4)             // 196608
#define NROPE (L_ * 32)             //  16384

// Scratch (device globals — no runtime allocation allowed)
__device__ __nv_bfloat16 g_abf[MROWS * HID];    // inputs bf16 [4096 x 768]
__device__ __nv_bfloat16 g_wt[OUTD * HID];      // W^T bf16 [1536 x 768] K-major
__device__ __nv_bfloat16 g_q[BHN * L_ * D_];    // q, (bh, l, d) bf16
__device__ __nv_bfloat16 g_k[BHN * L_ * D_];    // k, (bh, l, d) bf16
__device__ float         g_sin[NROPE];
__device__ float         g_cos[NROPE];

// All 16 128x128 tiles of the 512x512 logits: first 10 = upper (compute),
// last 6 = strictly-below-diagonal (fill-only).
__device__ const signed char T16_M[16] = {0,0,0,0,1,1,1,2,2,3, 1,2,2,3,3,3};
__device__ const signed char T16_N[16] = {0,1,2,3,1,2,3,2,3,3, 0,0,1,0,1,2};

// ---------------------------------------------------------------------------
// PTX helpers
// ---------------------------------------------------------------------------
static __device__ __forceinline__ uint32_t smem_u32(const void* p) {
    uint32_t a;
    asm("{ .reg .u64 t; cvta.to.shared.u64 t, %1; cvt.u32.u64 %0, t; }" : "=r"(a) : "l"(p));
    return a;
}
static __device__ __forceinline__ void cp_async16_s(uint32_t saddr, const void* g) {
    asm volatile("cp.async.cg.shared.global [%0], [%1], 16;\n" :: "r"(saddr), "l"(g));
}
static __device__ __forceinline__ void cp_commit() {
    asm volatile("cp.async.commit_group;\n" ::: "memory");
}
static __device__ __forceinline__ void ldsm_x4(uint32_t* r, uint32_t addr) {
    asm volatile("ldmatrix.sync.aligned.m8n8.x4.shared.b16 {%0,%1,%2,%3}, [%4];"
                 : "=r"(r[0]), "=r"(r[1]), "=r"(r[2]), "=r"(r[3]) : "r"(addr));
}
static __device__ __forceinline__ void mma16816(float* d, const uint32_t* a, const uint32_t* b) {
    asm volatile(
        "mma.sync.aligned.m16n8k16.row.col.f32.bf16.bf16.f32 "
        "{%0,%1,%2,%3}, {%4,%5,%6,%7}, {%8,%9}, {%0,%1,%2,%3};"
        : "+f"(d[0]), "+f"(d[1]), "+f"(d[2]), "+f"(d[3])
        : "r"(a[0]), "r"(a[1]), "r"(a[2]), "r"(a[3]), "r"(b[0]), "r"(b[1]));
}

// ---------------------------------------------------------------------------
// Kernel 0: convert inputs to bf16 + RoPE tables.
// ---------------------------------------------------------------------------
static __device__ __forceinline__ void conv_a(const float* __restrict__ A, int j) {
    float4 v = reinterpret_cast<const float4*>(A)[j];
    __nv_bfloat162 lo = __floats2bfloat162_rn(v.x, v.y);
    __nv_bfloat162 hi = __floats2bfloat162_rn(v.z, v.w);
    reinterpret_cast<uint2*>(g_abf)[j] =
        make_uint2(*reinterpret_cast<unsigned*>(&lo), *reinterpret_cast<unsigned*>(&hi));
}

__global__ __launch_bounds__(256) void prep_kernel(const float* __restrict__ A) {
    int idx = blockIdx.x * 256 + threadIdx.x;
    if (idx < NAQ) {
        conv_a(A, idx);
        conv_a(A, idx + NAQ);
        conv_a(A, idx + 2 * NAQ);
        conv_a(A, idx + 3 * NAQ);
    } else if (idx < NAQ + NROPE) {
        int t = idx - NAQ;
        int l = t >> 5;
        int i = t & 31;
        float invf = exp2f((float)i * -0.41524101186092027f);
        float s, c;
        sincosf((float)l * invf, &s, &c);
        g_sin[t] = s;
        g_cos[t] = c;
    }
}

// ---------------------------------------------------------------------------
// Kernel 0b: W [768 x 1536] f32 -> g_wt [1536 x 768] bf16 (tiled transpose)
// ---------------------------------------------------------------------------
__global__ __launch_bounds__(256) void wtrans_kernel(const float* __restrict__ W) {
    __shared__ float t[32][33];
    int n0 = blockIdx.x * 32, k0 = blockIdx.y * 32;
    int tx = threadIdx.x & 31, ty = threadIdx.x >> 5;   // 32x8
    #pragma unroll
    for (int i = 0; i < 4; i++)
        t[ty + i*8][tx] = W[(size_t)(k0 + ty + i*8) * OUTD + n0 + tx];
    __syncthreads();
    #pragma unroll
    for (int i = 0; i < 4; i++)
        g_wt[(size_t)(n0 + ty + i*8) * HID + k0 + tx] = __float2bfloat16(t[tx][ty + i*8]);
}

// ---------------------------------------------------------------------------
// Kernel 1: x = inputs @ W via mma.sync, bias+RoPE in registers, bf16 q/k out.
// Block 128m x 128n (one head), 8 warps (2x4), warp 64m x 32n.
// A: 4x ldsm_x4; B: 2x paired ldsm_x4. BK=32, 3-stage cp.async pipeline.
// ---------------------------------------------------------------------------
#define G1_ROWB   80                        // bytes per smem row (32 bf16 + pad)
#define G1_OPB    (128 * G1_ROWB)           // 10240 per operand
#define G1_STAGE  (2 * G1_OPB)              // 20480
#define G1_SMEM   (3 * G1_STAGE)            // 61440

__global__ __launch_bounds__(256, 2) void gemm1_kernel(const float* __restrict__ bias) {
    extern __shared__ __align__(16) unsigned char dsm[];
    __shared__ float bias_s[128];

    const int tid  = threadIdx.x;
    const int lane = tid & 31;
    const int w    = tid >> 5;
    const int wm   = w >> 2;             // 0..1 (m offset 64)
    const int wn   = w & 3;              // 0..3 (n offset 32)
    const int h    = blockIdx.x;
    const int m0   = blockIdx.y * 128;
    const int n0   = h * 128;

    if (tid < 128) bias_s[tid] = __ldg(&bias[n0 + tid]);

    const uint32_t sbase = smem_u32(dsm);

    // copy one BK=32 stage: A rows [m0..+128), B rows (g_wt) [n0..+128)
    auto copy_stage = [&](int kt) {
        uint32_t base = sbase + (kt % 3) * G1_STAGE;
        int k0e = kt * 32;
        #pragma unroll
        for (int it = 0; it < 4; it++) {
            int idx = tid + it * 256;            // 0..1023
            int r = (idx >> 2) & 127;
            int c = idx & 3;                     // 16B chunk
            if (idx < 512)
                cp_async16_s(base + r * G1_ROWB + c * 16,
                             &g_abf[(size_t)(m0 + r) * HID + k0e + c * 8]);
            else
                cp_async16_s(base + G1_OPB + r * G1_ROWB + c * 16,
                             &g_wt[(size_t)(n0 + r) * HID + k0e + c * 8]);
        }
    };

    // per-thread ldmatrix address offsets (relative to stage base)
    uint32_t a_off[4], b_off[2];
    #pragma unroll
    for (int mi = 0; mi < 4; mi++)
        a_off[mi] = (uint32_t)((wm*64 + mi*16 + (lane & 15)) * G1_ROWB + ((lane >> 4) * 16));
    #pragma unroll
    for (int p = 0; p < 2; p++)
        b_off[p] = (uint32_t)(G1_OPB + (wn*32 + p*16 + (lane & 15)) * G1_ROWB + ((lane >> 4) * 16));

    float acc[4][4][4];
    #pragma unroll
    for (int mi = 0; mi < 4; mi++)
        #pragma unroll
        for (int nj = 0; nj < 4; nj++)
            #pragma unroll
            for (int x = 0; x < 4; x++)
                acc[mi][nj][x] = 0.0f;

    copy_stage(0); cp_commit();
    copy_stage(1); cp_commit();

    const int NT = HID / 32;   // 24
    for (int kt = 0; kt < NT; kt++) {
        if (kt + 2 < NT) {
            copy_stage(kt + 2); cp_commit();
            asm volatile("cp.async.wait_group 2;" ::: "memory");
        } else if (kt + 1 < NT) {
            asm volatile("cp.async.wait_group 1;" ::: "memory");
        } else {
            asm volatile("cp.async.wait_group 0;" ::: "memory");
        }
        __syncthreads();

        uint32_t stg = sbase + (kt % 3) * G1_STAGE;
        #pragma unroll
        for (int ks = 0; ks < 2; ks++) {         // two k16 steps per BK=32
            uint32_t koff = ks * 32;             // 16 halfwords = 32B
            uint32_t a[4][4], bp[2][4];
            #pragma unroll
            for (int mi = 0; mi < 4; mi++)
                ldsm_x4(a[mi], stg + a_off[mi] + koff);
            #pragma unroll
            for (int p = 0; p < 2; p++)
                ldsm_x4(bp[p], stg + b_off[p] + koff);
            #pragma unroll
            for (int mi = 0; mi < 4; mi++)
                #pragma unroll
                for (int nj = 0; nj < 4; nj++) {
                    uint32_t bb[2] = { bp[nj >> 1][nj & 1], bp[nj >> 1][(nj & 1) + 2] };
                    mma16816(acc[mi][nj], a[mi], bb);
                }
        }
        __syncthreads();
    }

    // Epilogue: bias + RoPE in registers, store bf16x2 to g_q / g_k.
    __nv_bfloat16* dst = (wn < 2) ? g_q : g_k;
    float bv[4][2];
    #pragma unroll
    for (int nj = 0; nj < 4; nj++) {
        int nl = wn*32 + nj*8 + (lane & 3) * 2;
        bv[nj][0] = bias_s[nl];
        bv[nj][1] = bias_s[nl + 1];
    }

    #pragma unroll
    for (int mi = 0; mi < 4; mi++) {
        #pragma unroll
        for (int rh = 0; rh < 2; rh++) {
            int m_g = m0 + wm*64 + mi*16 + (lane >> 2) + rh*8;
            int l = m_g & (L_ - 1);
            int bidx = m_g >> 9;
            size_t rowp = ((size_t)(bidx * H_ + h) * L_ + l) * D_;
            #pragma unroll
            for (int nj = 0; nj < 4; nj++) {
                float x1 = acc[mi][nj][rh*2 + 0] + bv[nj][0];
                float x2 = acc[mi][nj][rh*2 + 1] + bv[nj][1];
                int nl = wn*32 + nj*8 + (lane & 3) * 2;
                int d  = nl & 63;
                int i  = d >> 1;
                float s = g_sin[l * 32 + i];
                float c = g_cos[l * 32 + i];
                __nv_bfloat162 pr = __floats2bfloat162_rn(x1 * c - x2 * s, x1 * s + x2 * c);
                *reinterpret_cast<uint32_t*>(&dst[rowp + d]) = *reinterpret_cast<uint32_t*>(&pr);
            }
        }
    }
}

// ---------------------------------------------------------------------------
// Kernel 2: logits = (q @ k^T)/8 over ALL 16 tiles; below-diagonal tiles take
// a store-only fast path. mma.sync, 8 warps (2x4), warp 64m x 32n.
// ---------------------------------------------------------------------------
#define AT_ROWB 144    // 64 bf16 (128B) + 16B pad

__global__ __launch_bounds__(256, 2) void attn_kernel(const int* __restrict__ am,
                                                      float* __restrict__ out) {
    const int bh = blockIdx.y;
    const int tm = (int)T16_M[blockIdx.x];
    const int tn = (int)T16_N[blockIdx.x];
    const int m0 = tm * 128, n0 = tn * 128;
    float* obase = out + (size_t)bh * L_ * L_;
    const float NEG = __int_as_float(0xFF7FFFFF);  // -FLT_MAX == finfo(f32).min
    const int tid  = threadIdx.x;

    if (tm > tn) {   // fill-only tile
        float4 negv = make_float4(NEG, NEG, NEG, NEG);
        #pragma unroll
        for (int it = 0; it < 16; it++) {
            int idx = tid + it * 256;          // 0..4095
            int r = idx >> 5;
            int c = (idx & 31) << 2;
            *reinterpret_cast<float4*>(&obase[(size_t)(m0 + r) * L_ + n0 + c]) = negv;
        }
        return;
    }

    const int b    = bh / H_;
    const int lane = tid & 31;
    const int w    = tid >> 5;
    const int wm   = w >> 2;     // 0..1
    const int wn   = w & 3;      // 0..3

    __shared__ __align__(16) unsigned char qmem[128 * AT_ROWB];
    __shared__ __align__(16) unsigned char kmem[128 * AT_ROWB];
    __shared__ unsigned char rowv[128];
    __shared__ unsigned char colv[128];

    const int* amb = am + b * L_;
    if (tid < 128)       rowv[tid]       = (unsigned char)(amb[m0 + tid] != 0);
    else                 colv[tid - 128] = (unsigned char)(amb[n0 + tid - 128] != 0);

    const __nv_bfloat16* qb = &g_q[(size_t)bh * L_ * D_];
    const __nv_bfloat16* kb = &g_k[(size_t)bh * L_ * D_];

    // 128 rows x 64 cols bf16 = 128B per row = 8 uint4; 1024 uint4 per matrix
    #pragma unroll
    for (int it = 0; it < 4; it++) {
        int idx = tid + it * 256;              // 0..1023
        int r = idx >> 3;
        int c = (idx & 7) << 4;                // byte offset within row
        const unsigned char* qsrc = reinterpret_cast<const unsigned char*>(qb + (size_t)(m0 + r) * D_);
        const unsigned char* ksrc = reinterpret_cast<const unsigned char*>(kb + (size_t)(n0 + r) * D_);
        *reinterpret_cast<uint4*>(qmem + r * AT_ROWB + c) =
            *reinterpret_cast<const uint4*>(qsrc + c);
        *reinterpret_cast<uint4*>(kmem + r * AT_ROWB + c) =
            *reinterpret_cast<const uint4*>(ksrc + c);
    }
    __syncthreads();

    const uint32_t qbase = smem_u32(qmem);
    const uint32_t kbase = smem_u32(kmem);

    uint32_t a_off[4], b_off[2];
    #pragma unroll
    for (int mi = 0; mi < 4; mi++)
        a_off[mi] = qbase + (uint32_t)((wm*64 + mi*16 + (lane & 15)) * AT_ROWB + ((lane >> 4) * 16));
    #pragma unroll
    for (int p = 0; p < 2; p++)
        b_off[p] = kbase + (uint32_t)((wn*32 + p*16 + (lane & 15)) * AT_ROWB + ((lane >> 4) * 16));

    float acc[4][4][4];
    #pragma unroll
    for (int mi = 0; mi < 4; mi++)
        #pragma unroll
        for (int nj = 0; nj < 4; nj++)
            #pragma unroll
            for (int x = 0; x < 4; x++)
                acc[mi][nj][x] = 0.0f;

    #pragma unroll
    for (int ks = 0; ks < 4; ks++) {           // D=64 -> 4 k16 steps
        uint32_t koff = ks * 32;               // 16 halfwords
        uint32_t a[4][4], bp[2][4];
        #pragma unroll
        for (int mi = 0; mi < 4; mi++)
            ldsm_x4(a[mi], a_off[mi] + koff);
        #pragma unroll
        for (int p = 0; p < 2; p++)
            ldsm_x4(bp[p], b_off[p] + koff);
        #pragma unroll
        for (int mi = 0; mi < 4; mi++)
            #pragma unroll
            for (int nj = 0; nj < 4; nj++) {
                uint32_t bb[2] = { bp[nj >> 1][nj & 1], bp[nj >> 1][(nj & 1) + 2] };
                mma16816(acc[mi][nj], a[mi], bb);
            }
    }

    // Masked register epilogue: float2 stores.
    #pragma unroll
    for (int mi = 0; mi < 4; mi++) {
        #pragma unroll
        for (int rh = 0; rh < 2; rh++) {
            int r_loc = wm*64 + mi*16 + (lane >> 2) + rh*8;
            int m = m0 + r_loc;
            bool rowok = (rowv[r_loc] != 0);
            #pragma unroll
            for (int nj = 0; nj < 4; nj++) {
                int n_loc = wn*32 + nj*8 + (lane & 3) * 2;
                int n = n0 + n_loc;
                float e0 = acc[mi][nj][rh*2 + 0] * 0.125f;
                float e1 = acc[mi][nj][rh*2 + 1] * 0.125f;
                bool v0 = rowok && colv[n_loc]     && (m <= n);
                bool v1 = rowok && colv[n_loc + 1] && (m <= n + 1);
                float2 val;
                val.x = v0 ? e0 : NEG;
                val.y = v1 ? e1 : NEG;
                *reinterpret_cast<float2*>(&obase[(size_t)m * L_ + n]) = val;
            }
        }
    }
}

// ---------------------------------------------------------------------------
extern "C" void kernel_launch(void* const* d_in, const int* in_sizes, int n_in,
                              void* d_out, int out_size) {
    const float* inputs = (const float*)d_in[0];
    const float* W      = (const float*)d_in[1];
    const float* bias   = (const float*)d_in[2];
    const int*   am     = (const int*)d_in[3];
    float* out = (float*)d_out;

    cudaFuncSetAttribute(gemm1_kernel, cudaFuncAttributeMaxDynamicSharedMemorySize, G1_SMEM);

    prep_kernel<<<(NAQ + NROPE + 255) / 256, 256>>>(inputs);
    wtrans_kernel<<<dim3(OUTD / 32, HID / 32), 256>>>(W);
    gemm1_kernel<<<dim3(H_, MROWS / 128), 256, G1_SMEM>>>(bias);
    attn_kernel<<<dim3(16, BHN), 256>>>(am, out);
}

// round 12
// speedup vs baseline: 1.3228x; 1.1559x over previous
#include <cuda_runtime.h>
#include <cuda_bf16.h>
#include <cuda_fp8.h>
#include <cstdint>

#define B_    8
#define L_    512
#define H_    12
#define D_    64
#define HID   768
#define OUTD  1536
#define MROWS 4096          // B_*L_
#define BHN   96            // B_*H_

#define NA4   (MROWS * HID / 4)     // 786432 float4 units of A
#define NAQ   (NA4 / 4)             // 196608
#define NROPE (L_ * 32)             //  16384

// Scratch (device globals — no runtime allocation allowed)
__device__ unsigned char g_a8[MROWS * HID];     // inputs e4m3 [4096 x 768]
__device__ unsigned char g_wt8[OUTD * HID];     // W^T e4m3 [1536 x 768] K-major
__device__ unsigned char g_q8[BHN * L_ * D_];   // q, (bh, l, d) e4m3
__device__ unsigned char g_k8[BHN * L_ * D_];   // k, (bh, l, d) e4m3
__device__ float         g_sin[NROPE];
__device__ float         g_cos[NROPE];

// All 16 128x128 tiles of the 512x512 logits: first 10 = upper (compute),
// last 6 = strictly-below-diagonal (fill-only).
__device__ const signed char T16_M[16] = {0,0,0,0,1,1,1,2,2,3, 1,2,2,3,3,3};
__device__ const signed char T16_N[16] = {0,1,2,3,1,2,3,2,3,3, 0,0,1,0,1,2};

// ---------------------------------------------------------------------------
// PTX helpers
// ---------------------------------------------------------------------------
static __device__ __forceinline__ uint32_t smem_u32(const void* p) {
    uint32_t a;
    asm("{ .reg .u64 t; cvta.to.shared.u64 t, %1; cvt.u32.u64 %0, t; }" : "=r"(a) : "l"(p));
    return a;
}
static __device__ __forceinline__ void cp_async16_s(uint32_t saddr, const void* g) {
    asm volatile("cp.async.cg.shared.global [%0], [%1], 16;\n" :: "r"(saddr), "l"(g));
}
static __device__ __forceinline__ void cp_commit() {
    asm volatile("cp.async.commit_group;\n" ::: "memory");
}
static __device__ __forceinline__ void ldsm_x4(uint32_t* r, uint32_t addr) {
    asm volatile("ldmatrix.sync.aligned.m8n8.x4.shared.b16 {%0,%1,%2,%3}, [%4];"
                 : "=r"(r[0]), "=r"(r[1]), "=r"(r[2]), "=r"(r[3]) : "r"(addr));
}
// fp8 e4m3 MMA: D(16x8 f32) += A(16x32) * B(8x32)^T
static __device__ __forceinline__ void mma16832(float* d, const uint32_t* a, const uint32_t* b) {
    asm volatile(
        "mma.sync.aligned.m16n8k32.row.col.f32.e4m3.e4m3.f32 "
        "{%0,%1,%2,%3}, {%4,%5,%6,%7}, {%8,%9}, {%0,%1,%2,%3};"
        : "+f"(d[0]), "+f"(d[1]), "+f"(d[2]), "+f"(d[3])
        : "r"(a[0]), "r"(a[1]), "r"(a[2]), "r"(a[3]), "r"(b[0]), "r"(b[1]));
}
static __device__ __forceinline__ unsigned short f2_to_e4m3x2(float x, float y) {
    return (unsigned short)__nv_cvt_float2_to_fp8x2(make_float2(x, y), __NV_SATFINITE, __NV_E4M3);
}

// ---------------------------------------------------------------------------
// Kernel 0: convert inputs to e4m3 + RoPE tables.
// ---------------------------------------------------------------------------
static __device__ __forceinline__ void conv_a(const float* __restrict__ A, int j) {
    float4 v = reinterpret_cast<const float4*>(A)[j];
    uint32_t lo = f2_to_e4m3x2(v.x, v.y);
    uint32_t hi = f2_to_e4m3x2(v.z, v.w);
    reinterpret_cast<uint32_t*>(g_a8)[j] = lo | (hi << 16);
}

__global__ __launch_bounds__(256) void prep_kernel(const float* __restrict__ A) {
    int idx = blockIdx.x * 256 + threadIdx.x;
    if (idx < NAQ) {
        conv_a(A, idx);
        conv_a(A, idx + NAQ);
        conv_a(A, idx + 2 * NAQ);
        conv_a(A, idx + 3 * NAQ);
    } else if (idx < NAQ + NROPE) {
        int t = idx - NAQ;
        int l = t >> 5;
        int i = t & 31;
        float invf = exp2f((float)i * -0.41524101186092027f);
        float s, c;
        sincosf((float)l * invf, &s, &c);
        g_sin[t] = s;
        g_cos[t] = c;
    }
}

// ---------------------------------------------------------------------------
// Kernel 0b: W [768 x 1536] f32 -> g_wt8 [1536 x 768] e4m3 (tiled transpose)
// ---------------------------------------------------------------------------
__global__ __launch_bounds__(256) void wtrans_kernel(const float* __restrict__ W) {
    __shared__ float t[32][33];
    int n0 = blockIdx.x * 32, k0 = blockIdx.y * 32;
    int tx = threadIdx.x & 31, ty = threadIdx.x >> 5;   // 32x8
    #pragma unroll
    for (int i = 0; i < 4; i++)
        t[ty + i*8][tx] = W[(size_t)(k0 + ty + i*8) * OUTD + n0 + tx];
    __syncthreads();
    #pragma unroll
    for (int i = 0; i < 4; i++)
        g_wt8[(size_t)(n0 + ty + i*8) * HID + k0 + tx] =
            (unsigned char)__nv_cvt_float_to_fp8(t[tx][ty + i*8], __NV_SATFINITE, __NV_E4M3);
}

// ---------------------------------------------------------------------------
// Kernel 1: x = inputs @ W via fp8 mma.sync, bias+RoPE in registers, e4m3 out.
// Block 128m x 128n (one head), 8 warps (2x4), warp 64m x 32n.
// BK=64 (64B rows), 3-stage cp.async pipeline. 2 k32 steps per stage.
// ---------------------------------------------------------------------------
#define G1_ROWB   80                        // bytes per smem row (64 fp8 + pad)
#define G1_OPB    (128 * G1_ROWB)           // 10240 per operand
#define G1_STAGE  (2 * G1_OPB)              // 20480
#define G1_SMEM   (3 * G1_STAGE)            // 61440

__global__ __launch_bounds__(256, 2) void gemm1_kernel(const float* __restrict__ bias) {
    extern __shared__ __align__(16) unsigned char dsm[];
    __shared__ float bias_s[128];

    const int tid  = threadIdx.x;
    const int lane = tid & 31;
    const int w    = tid >> 5;
    const int wm   = w >> 2;             // 0..1 (m offset 64)
    const int wn   = w & 3;              // 0..3 (n offset 32)
    const int h    = blockIdx.x;
    const int m0   = blockIdx.y * 128;
    const int n0   = h * 128;

    if (tid < 128) bias_s[tid] = __ldg(&bias[n0 + tid]);

    const uint32_t sbase = smem_u32(dsm);

    // copy one BK=64 stage: A rows [m0..+128), B rows (g_wt8) [n0..+128)
    auto copy_stage = [&](int kt) {
        uint32_t base = sbase + (kt % 3) * G1_STAGE;
        int k0e = kt * 64;
        #pragma unroll
        for (int it = 0; it < 4; it++) {
            int idx = tid + it * 256;            // 0..1023
            int r = (idx >> 2) & 127;
            int c = idx & 3;                     // 16B chunk (16 fp8)
            if (idx < 512)
                cp_async16_s(base + r * G1_ROWB + c * 16,
                             &g_a8[(size_t)(m0 + r) * HID + k0e + c * 16]);
            else
                cp_async16_s(base + G1_OPB + r * G1_ROWB + c * 16,
                             &g_wt8[(size_t)(n0 + r) * HID + k0e + c * 16]);
        }
    };

    // per-thread ldmatrix address offsets (relative to stage base)
    uint32_t a_off[4], b_off[2];
    #pragma unroll
    for (int mi = 0; mi < 4; mi++)
        a_off[mi] = (uint32_t)((wm*64 + mi*16 + (lane & 15)) * G1_ROWB + ((lane >> 4) * 16));
    #pragma unroll
    for (int p = 0; p < 2; p++)
        b_off[p] = (uint32_t)(G1_OPB + (wn*32 + p*16 + (lane & 15)) * G1_ROWB + ((lane >> 4) * 16));

    float acc[4][4][4];
    #pragma unroll
    for (int mi = 0; mi < 4; mi++)
        #pragma unroll
        for (int nj = 0; nj < 4; nj++)
            #pragma unroll
            for (int x = 0; x < 4; x++)
                acc[mi][nj][x] = 0.0f;

    copy_stage(0); cp_commit();
    copy_stage(1); cp_commit();

    const int NT = HID / 64;   // 12
    for (int kt = 0; kt < NT; kt++) {
        if (kt + 2 < NT) {
            copy_stage(kt + 2); cp_commit();
            asm volatile("cp.async.wait_group 2;" ::: "memory");
        } else if (kt + 1 < NT) {
            asm volatile("cp.async.wait_group 1;" ::: "memory");
        } else {
            asm volatile("cp.async.wait_group 0;" ::: "memory");
        }
        __syncthreads();

        uint32_t stg = sbase + (kt % 3) * G1_STAGE;
        #pragma unroll
        for (int ks = 0; ks < 2; ks++) {         // two k32 steps per BK=64
            uint32_t koff = ks * 32;             // 32 bytes
            uint32_t a[4][4], bp[2][4];
            #pragma unroll
            for (int mi = 0; mi < 4; mi++)
                ldsm_x4(a[mi], stg + a_off[mi] + koff);
            #pragma unroll
            for (int p = 0; p < 2; p++)
                ldsm_x4(bp[p], stg + b_off[p] + koff);
            #pragma unroll
            for (int mi = 0; mi < 4; mi++)
                #pragma unroll
                for (int nj = 0; nj < 4; nj++) {
                    uint32_t bb[2] = { bp[nj >> 1][nj & 1], bp[nj >> 1][(nj & 1) + 2] };
                    mma16832(acc[mi][nj], a[mi], bb);
                }
        }
        __syncthreads();
    }

    // Epilogue: bias + RoPE in registers, store e4m3x2 to g_q8 / g_k8.
    unsigned char* dst = (wn < 2) ? g_q8 : g_k8;
    float bv[4][2];
    #pragma unroll
    for (int nj = 0; nj < 4; nj++) {
        int nl = wn*32 + nj*8 + (lane & 3) * 2;
        bv[nj][0] = bias_s[nl];
        bv[nj][1] = bias_s[nl + 1];
    }

    #pragma unroll
    for (int mi = 0; mi < 4; mi++) {
        #pragma unroll
        for (int rh = 0; rh < 2; rh++) {
            int m_g = m0 + wm*64 + mi*16 + (lane >> 2) + rh*8;
            int l = m_g & (L_ - 1);
            int bidx = m_g >> 9;
            size_t rowp = ((size_t)(bidx * H_ + h) * L_ + l) * D_;
            #pragma unroll
            for (int nj = 0; nj < 4; nj++) {
                float x1 = acc[mi][nj][rh*2 + 0] + bv[nj][0];
                float x2 = acc[mi][nj][rh*2 + 1] + bv[nj][1];
                int nl = wn*32 + nj*8 + (lane & 3) * 2;
                int d  = nl & 63;
                int i  = d >> 1;
                float s = g_sin[l * 32 + i];
                float c = g_cos[l * 32 + i];
                unsigned short pr = f2_to_e4m3x2(x1 * c - x2 * s, x1 * s + x2 * c);
                *reinterpret_cast<unsigned short*>(&dst[rowp + d]) = pr;
            }
        }
    }
}

// ---------------------------------------------------------------------------
// Kernel 2: logits = (q @ k^T)/8 over ALL 16 tiles; below-diagonal tiles take
// a store-only fast path. fp8 mma.sync, 8 warps (2x4), warp 64m x 32n.
// ---------------------------------------------------------------------------
#define AT_ROWB 80    // 64 fp8 (64B) + 16B pad

__global__ __launch_bounds__(256, 2) void attn_kernel(const int* __restrict__ am,
                                                      float* __restrict__ out) {
    const int bh = blockIdx.y;
    const int tm = (int)T16_M[blockIdx.x];
    const int tn = (int)T16_N[blockIdx.x];
    const int m0 = tm * 128, n0 = tn * 128;
    float* obase = out + (size_t)bh * L_ * L_;
    const float NEG = __int_as_float(0xFF7FFFFF);  // -FLT_MAX == finfo(f32).min
    const int tid  = threadIdx.x;

    if (tm > tn) {   // fill-only tile
        float4 negv = make_float4(NEG, NEG, NEG, NEG);
        #pragma unroll
        for (int it = 0; it < 16; it++) {
            int idx = tid + it * 256;          // 0..4095
            int r = idx >> 5;
            int c = (idx & 31) << 2;
            *reinterpret_cast<float4*>(&obase[(size_t)(m0 + r) * L_ + n0 + c]) = negv;
        }
        return;
    }

    const int b    = bh / H_;
    const int lane = tid & 31;
    const int w    = tid >> 5;
    const int wm   = w >> 2;     // 0..1
    const int wn   = w & 3;      // 0..3

    __shared__ __align__(16) unsigned char qmem[128 * AT_ROWB];
    __shared__ __align__(16) unsigned char kmem[128 * AT_ROWB];
    __shared__ unsigned char rowv[128];
    __shared__ unsigned char colv[128];

    const int* amb = am + b * L_;
    if (tid < 128)       rowv[tid]       = (unsigned char)(amb[m0 + tid] != 0);
    else                 colv[tid - 128] = (unsigned char)(amb[n0 + tid - 128] != 0);

    const unsigned char* qb = &g_q8[(size_t)bh * L_ * D_];
    const unsigned char* kb = &g_k8[(size_t)bh * L_ * D_];

    // 128 rows x 64B per row = 512 uint4 per matrix; 2 per thread each
    #pragma unroll
    for (int it = 0; it < 2; it++) {
        int idx = tid + it * 256;              // 0..511
        int r = idx >> 2;
        int c = (idx & 3) << 4;                // byte offset within row
        *reinterpret_cast<uint4*>(qmem + r * AT_ROWB + c) =
            *reinterpret_cast<const uint4*>(qb + (size_t)(m0 + r) * D_ + c);
        *reinterpret_cast<uint4*>(kmem + r * AT_ROWB + c) =
            *reinterpret_cast<const uint4*>(kb + (size_t)(n0 + r) * D_ + c);
    }
    __syncthreads();

    const uint32_t qbase = smem_u32(qmem);
    const uint32_t kbase = smem_u32(kmem);

    uint32_t a_off[4], b_off[2];
    #pragma unroll
    for (int mi = 0; mi < 4; mi++)
        a_off[mi] = qbase + (uint32_t)((wm*64 + mi*16 + (lane & 15)) * AT_ROWB + ((lane >> 4) * 16));
    #pragma unroll
    for (int p = 0; p < 2; p++)
        b_off[p] = kbase + (uint32_t)((wn*32 + p*16 + (lane & 15)) * AT_ROWB + ((lane >> 4) * 16));

    float acc[4][4][4];
    #pragma unroll
    for (int mi = 0; mi < 4; mi++)
        #pragma unroll
        for (int nj = 0; nj < 4; nj++)
            #pragma unroll
            for (int x = 0; x < 4; x++)
                acc[mi][nj][x] = 0.0f;

    #pragma unroll
    for (int ks = 0; ks < 2; ks++) {           // D=64 -> 2 k32 steps
        uint32_t koff = ks * 32;               // 32 bytes
        uint32_t a[4][4], bp[2][4];
        #pragma unroll
        for (int mi = 0; mi < 4; mi++)
            ldsm_x4(a[mi], a_off[mi] + koff);
        #pragma unroll
        for (int p = 0; p < 2; p++)
            ldsm_x4(bp[p], b_off[p] + koff);
        #pragma unroll
        for (int mi = 0; mi < 4; mi++)
            #pragma unroll
            for (int nj = 0; nj < 4; nj++) {
                uint32_t bb[2] = { bp[nj >> 1][nj & 1], bp[nj >> 1][(nj & 1) + 2] };
                mma16832(acc[mi][nj], a[mi], bb);
            }
    }

    // Masked register epilogue: float2 stores.
    #pragma unroll
    for (int mi = 0; mi < 4; mi++) {
        #pragma unroll
        for (int rh = 0; rh < 2; rh++) {
            int r_loc = wm*64 + mi*16 + (lane >> 2) + rh*8;
            int m = m0 + r_loc;
            bool rowok = (rowv[r_loc] != 0);
            #pragma unroll
            for (int nj = 0; nj < 4; nj++) {
                int n_loc = wn*32 + nj*8 + (lane & 3) * 2;
                int n = n0 + n_loc;
                float e0 = acc[mi][nj][rh*2 + 0] * 0.125f;
                float e1 = acc[mi][nj][rh*2 + 1] * 0.125f;
                bool v0 = rowok && colv[n_loc]     && (m <= n);
                bool v1 = rowok && colv[n_loc + 1] && (m <= n + 1);
                float2 val;
                val.x = v0 ? e0 : NEG;
                val.y = v1 ? e1 : NEG;
                *reinterpret_cast<float2*>(&obase[(size_t)m * L_ + n]) = val;
            }
        }
    }
}

// ---------------------------------------------------------------------------
extern "C" void kernel_launch(void* const* d_in, const int* in_sizes, int n_in,
                              void* d_out, int out_size) {
    const float* inputs = (const float*)d_in[0];
    const float* W      = (const float*)d_in[1];
    const float* bias   = (const float*)d_in[2];
    const int*   am     = (const int*)d_in[3];
    float* out = (float*)d_out;

    cudaFuncSetAttribute(gemm1_kernel, cudaFuncAttributeMaxDynamicSharedMemorySize, G1_SMEM);

    prep_kernel<<<(NAQ + NROPE + 255) / 256, 256>>>(inputs);
    wtrans_kernel<<<dim3(OUTD / 32, HID / 32), 256>>>(W);
    gemm1_kernel<<<dim3(H_, MROWS / 128), 256, G1_SMEM>>>(bias);
    attn_kernel<<<dim3(16, BHN), 256>>>(am, out);
}

// round 14
// speedup vs baseline: 1.3482x; 1.0192x over previous
#include <cuda_runtime.h>
#include <cuda_bf16.h>
#include <cuda_fp8.h>
#include <cstdint>

#define B_    8
#define L_    512
#define H_    12
#define D_    64
#define HID   768
#define OUTD  1536
#define MROWS 4096          // B_*L_
#define BHN   96            // B_*H_

#define NA4   (MROWS * HID / 4)     // 786432 float4 units of A
#define NAQ   (NA4 / 4)             // 196608
#define NROPE (L_ * 32)             //  16384

// Scratch (device globals — no runtime allocation allowed)
__device__ unsigned char g_a8[MROWS * HID];     // inputs e4m3 [4096 x 768]
__device__ unsigned char g_wt8[OUTD * HID];     // W^T e4m3 [1536 x 768] K-major
__device__ unsigned char g_q8[BHN * L_ * D_];   // q, (bh, l, d) e4m3
__device__ unsigned char g_k8[BHN * L_ * D_];   // k, (bh, l, d) e4m3
__device__ float         g_sin[NROPE];
__device__ float         g_cos[NROPE];

// All 16 128x128 tiles of the 512x512 logits: first 10 = upper (compute),
// last 6 = strictly-below-diagonal (fill-only).
__device__ const signed char T16_M[16] = {0,0,0,0,1,1,1,2,2,3, 1,2,2,3,3,3};
__device__ const signed char T16_N[16] = {0,1,2,3,1,2,3,2,3,3, 0,0,1,0,1,2};

// ---------------------------------------------------------------------------
// PTX helpers
// ---------------------------------------------------------------------------
static __device__ __forceinline__ uint32_t smem_u32(const void* p) {
    uint32_t a;
    asm("{ .reg .u64 t; cvta.to.shared.u64 t, %1; cvt.u32.u64 %0, t; }" : "=r"(a) : "l"(p));
    return a;
}
static __device__ __forceinline__ void cp_async16_s(uint32_t saddr, const void* g) {
    asm volatile("cp.async.cg.shared.global [%0], [%1], 16;\n" :: "r"(saddr), "l"(g));
}
static __device__ __forceinline__ void cp_commit() {
    asm volatile("cp.async.commit_group;\n" ::: "memory");
}
static __device__ __forceinline__ void ldsm_x4(uint32_t* r, uint32_t addr) {
    asm volatile("ldmatrix.sync.aligned.m8n8.x4.shared.b16 {%0,%1,%2,%3}, [%4];"
                 : "=r"(r[0]), "=r"(r[1]), "=r"(r[2]), "=r"(r[3]) : "r"(addr));
}
// fp8 e4m3 MMA: D(16x8 f32) += A(16x32) * B(8x32)^T
static __device__ __forceinline__ void mma16832(float* d, const uint32_t* a, const uint32_t* b) {
    asm volatile(
        "mma.sync.aligned.m16n8k32.row.col.f32.e4m3.e4m3.f32 "
        "{%0,%1,%2,%3}, {%4,%5,%6,%7}, {%8,%9}, {%0,%1,%2,%3};"
        : "+f"(d[0]), "+f"(d[1]), "+f"(d[2]), "+f"(d[3])
        : "r"(a[0]), "r"(a[1]), "r"(a[2]), "r"(a[3]), "r"(b[0]), "r"(b[1]));
}
static __device__ __forceinline__ unsigned short f2_to_e4m3x2(float x, float y) {
    return (unsigned short)__nv_cvt_float2_to_fp8x2(make_float2(x, y), __NV_SATFINITE, __NV_E4M3);
}

// ---------------------------------------------------------------------------
// Kernel 0: convert inputs to e4m3 + RoPE tables.
// ---------------------------------------------------------------------------
static __device__ __forceinline__ void conv_a(const float* __restrict__ A, int j) {
    float4 v = reinterpret_cast<const float4*>(A)[j];
    uint32_t lo = f2_to_e4m3x2(v.x, v.y);
    uint32_t hi = f2_to_e4m3x2(v.z, v.w);
    reinterpret_cast<uint32_t*>(g_a8)[j] = lo | (hi << 16);
}

__global__ __launch_bounds__(256) void prep_kernel(const float* __restrict__ A) {
    int idx = blockIdx.x * 256 + threadIdx.x;
    if (idx < NAQ) {
        conv_a(A, idx);
        conv_a(A, idx + NAQ);
        conv_a(A, idx + 2 * NAQ);
        conv_a(A, idx + 3 * NAQ);
    } else if (idx < NAQ + NROPE) {
        int t = idx - NAQ;
        int l = t >> 5;
        int i = t & 31;
        float invf = exp2f((float)i * -0.41524101186092027f);
        float s, c;
        sincosf((float)l * invf, &s, &c);
        g_sin[t] = s;
        g_cos[t] = c;
    }
}

// ---------------------------------------------------------------------------
// Kernel 0b: W [768 x 1536] f32 -> g_wt8 [1536 x 768] e4m3 (tiled transpose)
// ---------------------------------------------------------------------------
__global__ __launch_bounds__(256) void wtrans_kernel(const float* __restrict__ W) {
    __shared__ float t[32][33];
    int n0 = blockIdx.x * 32, k0 = blockIdx.y * 32;
    int tx = threadIdx.x & 31, ty = threadIdx.x >> 5;   // 32x8
    #pragma unroll
    for (int i = 0; i < 4; i++)
        t[ty + i*8][tx] = W[(size_t)(k0 + ty + i*8) * OUTD + n0 + tx];
    __syncthreads();
    #pragma unroll
    for (int i = 0; i < 4; i++)
        g_wt8[(size_t)(n0 + ty + i*8) * HID + k0 + tx] =
            (unsigned char)__nv_cvt_float_to_fp8(t[tx][ty + i*8], __NV_SATFINITE, __NV_E4M3);
}

// ---------------------------------------------------------------------------
// Kernel 1: x = inputs @ W via fp8 mma.sync, bias+RoPE in registers, e4m3 out.
// Block 128m x 128n (one head), 8 warps (2x4), warp 64m x 32n.
// BK=128 (128B rows), 2-stage cp.async pipeline. 4 k32 steps per stage.
// ---------------------------------------------------------------------------
#define G1_ROWB   144                       // 128B fp8 data + 16B pad
#define G1_OPB    (128 * G1_ROWB)           // 18432 per operand
#define G1_STAGE  (2 * G1_OPB)              // 36864
#define G1_SMEM   (2 * G1_STAGE)            // 73728

__global__ __launch_bounds__(256, 2) void gemm1_kernel(const float* __restrict__ bias) {
    extern __shared__ __align__(16) unsigned char dsm[];
    __shared__ float bias_s[128];

    const int tid  = threadIdx.x;
    const int lane = tid & 31;
    const int w    = tid >> 5;
    const int wm   = w >> 2;             // 0..1 (m offset 64)
    const int wn   = w & 3;              // 0..3 (n offset 32)
    const int h    = blockIdx.x;
    const int m0   = blockIdx.y * 128;
    const int n0   = h * 128;

    if (tid < 128) bias_s[tid] = __ldg(&bias[n0 + tid]);

    const uint32_t sbase = smem_u32(dsm);

    // copy one BK=128 stage: A rows [m0..+128), B rows (g_wt8) [n0..+128)
    // 2 x (128 rows x 128B) = 2048 16B-chunks, 8 per thread.
    auto copy_stage = [&](int kt) {
        uint32_t base = sbase + (kt & 1) * G1_STAGE;
        int k0e = kt * 128;
        #pragma unroll
        for (int it = 0; it < 8; it++) {
            int idx = tid + it * 256;            // 0..2047
            int r = (idx >> 3) & 127;
            int c = idx & 7;                     // 16B chunk
            if (idx < 1024)
                cp_async16_s(base + r * G1_ROWB + c * 16,
                             &g_a8[(size_t)(m0 + r) * HID + k0e + c * 16]);
            else
                cp_async16_s(base + G1_OPB + r * G1_ROWB + c * 16,
                             &g_wt8[(size_t)(n0 + r) * HID + k0e + c * 16]);
        }
    };

    // per-thread ldmatrix address offsets (relative to stage base)
    uint32_t a_off[4], b_off[2];
    #pragma unroll
    for (int mi = 0; mi < 4; mi++)
        a_off[mi] = (uint32_t)((wm*64 + mi*16 + (lane & 15)) * G1_ROWB + ((lane >> 4) * 16));
    #pragma unroll
    for (int p = 0; p < 2; p++)
        b_off[p] = (uint32_t)(G1_OPB + (wn*32 + p*16 + (lane & 15)) * G1_ROWB + ((lane >> 4) * 16));

    float acc[4][4][4];
    #pragma unroll
    for (int mi = 0; mi < 4; mi++)
        #pragma unroll
        for (int nj = 0; nj < 4; nj++)
            #pragma unroll
            for (int x = 0; x < 4; x++)
                acc[mi][nj][x] = 0.0f;

    copy_stage(0); cp_commit();

    const int NT = HID / 128;   // 6
    for (int kt = 0; kt < NT; kt++) {
        if (kt + 1 < NT) {
            copy_stage(kt + 1); cp_commit();
            asm volatile("cp.async.wait_group 1;" ::: "memory");
        } else {
            asm volatile("cp.async.wait_group 0;" ::: "memory");
        }
        __syncthreads();

        uint32_t stg = sbase + (kt & 1) * G1_STAGE;
        #pragma unroll
        for (int ks = 0; ks < 4; ks++) {         // four k32 steps per BK=128
            uint32_t koff = ks * 32;             // 32 bytes
            uint32_t a[4][4], bp[2][4];
            #pragma unroll
            for (int mi = 0; mi < 4; mi++)
                ldsm_x4(a[mi], stg + a_off[mi] + koff);
            #pragma unroll
            for (int p = 0; p < 2; p++)
                ldsm_x4(bp[p], stg + b_off[p] + koff);
            #pragma unroll
            for (int mi = 0; mi < 4; mi++)
                #pragma unroll
                for (int nj = 0; nj < 4; nj++) {
                    uint32_t bb[2] = { bp[nj >> 1][nj & 1], bp[nj >> 1][(nj & 1) + 2] };
                    mma16832(acc[mi][nj], a[mi], bb);
                }
        }
        __syncthreads();
    }

    // Epilogue: bias + RoPE in registers, store e4m3x2 to g_q8 / g_k8.
    unsigned char* dst = (wn < 2) ? g_q8 : g_k8;
    float bv[4][2];
    #pragma unroll
    for (int nj = 0; nj < 4; nj++) {
        int nl = wn*32 + nj*8 + (lane & 3) * 2;
        bv[nj][0] = bias_s[nl];
        bv[nj][1] = bias_s[nl + 1];
    }

    #pragma unroll
    for (int mi = 0; mi < 4; mi++) {
        #pragma unroll
        for (int rh = 0; rh < 2; rh++) {
            int m_g = m0 + wm*64 + mi*16 + (lane >> 2) + rh*8;
            int l = m_g & (L_ - 1);
            int bidx = m_g >> 9;
            size_t rowp = ((size_t)(bidx * H_ + h) * L_ + l) * D_;
            #pragma unroll
            for (int nj = 0; nj < 4; nj++) {
                float x1 = acc[mi][nj][rh*2 + 0] + bv[nj][0];
                float x2 = acc[mi][nj][rh*2 + 1] + bv[nj][1];
                int nl = wn*32 + nj*8 + (lane & 3) * 2;
                int d  = nl & 63;
                int i  = d >> 1;
                float s = g_sin[l * 32 + i];
                float c = g_cos[l * 32 + i];
                unsigned short pr = f2_to_e4m3x2(x1 * c - x2 * s, x1 * s + x2 * c);
                *reinterpret_cast<unsigned short*>(&dst[rowp + d]) = pr;
            }
        }
    }
}

// ---------------------------------------------------------------------------
// Kernel 2: logits = (q @ k^T)/8 over ALL 16 tiles; below-diagonal tiles take
// a store-only fast path. fp8 mma.sync, 8 warps (2x4), warp 64m x 32n.
// Epilogue: two 64-row passes staged through smem -> coalesced float4 stores.
// ---------------------------------------------------------------------------
#define AT_ROWB 80    // 64 fp8 (64B) + 16B pad

__global__ __launch_bounds__(256, 2) void attn_kernel(const int* __restrict__ am,
                                                      float* __restrict__ out) {
    const int bh = blockIdx.y;
    const int tm = (int)T16_M[blockIdx.x];
    const int tn = (int)T16_N[blockIdx.x];
    const int m0 = tm * 128, n0 = tn * 128;
    float* obase = out + (size_t)bh * L_ * L_;
    const float NEG = __int_as_float(0xFF7FFFFF);  // -FLT_MAX == finfo(f32).min
    const int tid  = threadIdx.x;

    if (tm > tn) {   // fill-only tile
        float4 negv = make_float4(NEG, NEG, NEG, NEG);
        #pragma unroll
        for (int it = 0; it < 16; it++) {
            int idx = tid + it * 256;          // 0..4095
            int r = idx >> 5;
            int c = (idx & 31) << 2;
            *reinterpret_cast<float4*>(&obase[(size_t)(m0 + r) * L_ + n0 + c]) = negv;
        }
        return;
    }

    const int b    = bh / H_;
    const int lane = tid & 31;
    const int w    = tid >> 5;
    const int wm   = w >> 2;     // 0..1
    const int wn   = w & 3;      // 0..3

    // union: q/k tiles (2 x 10240 = 20480) then reused as Es 64x132 f32 (33792)
    __shared__ __align__(16) unsigned char smem_raw[64 * 132 * 4];
    __shared__ unsigned char rowv[128];
    __shared__ unsigned char colv[128];
    unsigned char* qmem = smem_raw;
    unsigned char* kmem = smem_raw + 128 * AT_ROWB;
    float (*Es)[132] = reinterpret_cast<float (*)[132]>(smem_raw);

    const int* amb = am + b * L_;
    if (tid < 128)       rowv[tid]       = (unsigned char)(amb[m0 + tid] != 0);
    else                 colv[tid - 128] = (unsigned char)(amb[n0 + tid - 128] != 0);

    const unsigned char* qb = &g_q8[(size_t)bh * L_ * D_];
    const unsigned char* kb = &g_k8[(size_t)bh * L_ * D_];

    // 128 rows x 64B per row = 512 uint4 per matrix; 2 per thread each
    #pragma unroll
    for (int it = 0; it < 2; it++) {
        int idx = tid + it * 256;              // 0..511
        int r = idx >> 2;
        int c = (idx & 3) << 4;                // byte offset within row
        *reinterpret_cast<uint4*>(qmem + r * AT_ROWB + c) =
            *reinterpret_cast<const uint4*>(qb + (size_t)(m0 + r) * D_ + c);
        *reinterpret_cast<uint4*>(kmem + r * AT_ROWB + c) =
            *reinterpret_cast<const uint4*>(kb + (size_t)(n0 + r) * D_ + c);
    }
    __syncthreads();

    const uint32_t qbase = smem_u32(qmem);
    const uint32_t kbase = smem_u32(kmem);

    uint32_t a_off[4], b_off[2];
    #pragma unroll
    for (int mi = 0; mi < 4; mi++)
        a_off[mi] = qbase + (uint32_t)((wm*64 + mi*16 + (lane & 15)) * AT_ROWB + ((lane >> 4) * 16));
    #pragma unroll
    for (int p = 0; p < 2; p++)
        b_off[p] = kbase + (uint32_t)((wn*32 + p*16 + (lane & 15)) * AT_ROWB + ((lane >> 4) * 16));

    float acc[4][4][4];
    #pragma unroll
    for (int mi = 0; mi < 4; mi++)
        #pragma unroll
        for (int nj = 0; nj < 4; nj++)
            #pragma unroll
            for (int x = 0; x < 4; x++)
                acc[mi][nj][x] = 0.0f;

    #pragma unroll
    for (int ks = 0; ks < 2; ks++) {           // D=64 -> 2 k32 steps
        uint32_t koff = ks * 32;               // 32 bytes
        uint32_t a[4][4], bp[2][4];
        #pragma unroll
        for (int mi = 0; mi < 4; mi++)
            ldsm_x4(a[mi], a_off[mi] + koff);
        #pragma unroll
        for (int p = 0; p < 2; p++)
            ldsm_x4(bp[p], b_off[p] + koff);
        #pragma unroll
        for (int mi = 0; mi < 4; mi++)
            #pragma unroll
            for (int nj = 0; nj < 4; nj++) {
                uint32_t bb[2] = { bp[nj >> 1][nj & 1], bp[nj >> 1][(nj & 1) + 2] };
                mma16832(acc[mi][nj], a[mi], bb);
            }
    }

    // Two 64-row passes: warps with wm==half stage their acc to Es, then all
    // 256 threads do masked coalesced float4 stores.
    #pragma unroll
    for (int half = 0; half < 2; half++) {
        __syncthreads();
        if (wm == half) {
            #pragma unroll
            for (int mi = 0; mi < 4; mi++)
                #pragma unroll
                for (int rh = 0; rh < 2; rh++) {
                    int row = mi*16 + (lane >> 2) + rh*8;   // 0..63
                    #pragma unroll
                    for (int nj = 0; nj < 4; nj++) {
                        int col = wn*32 + nj*8 + (lane & 3)*2;
                        float2 v2 = make_float2(acc[mi][nj][rh*2 + 0],
                                                acc[mi][nj][rh*2 + 1]);
                        *reinterpret_cast<float2*>(&Es[row][col]) = v2;
                    }
                }
        }
        __syncthreads();

        // 64 rows x 32 float4 = 2048 / 256 = 8 iterations
        #pragma unroll
        for (int it = 0; it < 8; it++) {
            int f = tid + it * 256;            // 0..2047
            int r = f >> 5;
            int c4 = (f & 31) << 2;
            int m = m0 + half * 64 + r;
            int n = n0 + c4;
            bool rowok = (rowv[half * 64 + r] != 0);
            uchar4 cv = *reinterpret_cast<const uchar4*>(&colv[c4]);
            float4 v;
            float e0 = Es[r][c4+0] * 0.125f;
            float e1 = Es[r][c4+1] * 0.125f;
            float e2 = Es[r][c4+2] * 0.125f;
            float e3 = Es[r][c4+3] * 0.125f;
            v.x = (rowok && cv.x && (m <= n+0)) ? e0 : NEG;
            v.y = (rowok && cv.y && (m <= n+1)) ? e1 : NEG;
            v.z = (rowok && cv.z && (m <= n+2)) ? e2 : NEG;
            v.w = (rowok && cv.w && (m <= n+3)) ? e3 : NEG;
            *reinterpret_cast<float4*>(&obase[(size_t)m * L_ + n]) = v;
        }
    }
}

// ---------------------------------------------------------------------------
extern "C" void kernel_launch(void* const* d_in, const int* in_sizes, int n_in,
                              void* d_out, int out_size) {
    const float* inputs = (const float*)d_in[0];
    const float* W      = (const float*)d_in[1];
    const float* bias   = (const float*)d_in[2];
    const int*   am     = (const int*)d_in[3];
    float* out = (float*)d_out;

    cudaFuncSetAttribute(gemm1_kernel, cudaFuncAttributeMaxDynamicSharedMemorySize, G1_SMEM);

    prep_kernel<<<(NAQ + NROPE + 255) / 256, 256>>>(inputs);
    wtrans_kernel<<<dim3(OUTD / 32, HID / 32), 256>>>(W);
    gemm1_kernel<<<dim3(H_, MROWS / 128), 256, G1_SMEM>>>(bias);
    attn_kernel<<<dim3(16, BHN), 256>>>(am, out);
}